// round 2
// baseline (speedup 1.0000x reference)
#include <cuda_runtime.h>
#include <math.h>

#define DIM    512
#define MAXNE  4096
#define MAXN   65536

#define BM 128
#define BE 128
#define KB 16

// ---------------- device scratch (no allocs allowed) ----------------
__device__ float g_inv_norm[MAXNE];
__device__ float g_scale[MAXNE];
__device__ int   g_ind[MAXN];
__device__ float g_diff;

// ---------------- K1: per-code norms (+ reset g_diff) ----------------
__global__ void norms_kernel(const float* __restrict__ w, int ne) {
    int row = blockIdx.x;
    if (row >= ne) return;
    const float* wr = w + (size_t)row * DIM;
    float s = 0.f;
    for (int i = threadIdx.x; i < DIM; i += 128) {
        float v = wr[i];
        s += v * v;
    }
    __shared__ float red[4];
    #pragma unroll
    for (int o = 16; o; o >>= 1) s += __shfl_down_sync(0xffffffffu, s, o);
    if ((threadIdx.x & 31) == 0) red[threadIdx.x >> 5] = s;
    __syncthreads();
    if (threadIdx.x == 0) {
        float t = red[0] + red[1] + red[2] + red[3];
        float n = sqrtf(t);
        g_inv_norm[row] = 1.0f / n;
        g_scale[row]    = fminf(1.0f, 1.0f / fmaxf(n, 1e-7f));
        if (row == 0) g_diff = 0.f;        // ordered before gather (same stream)
    }
}

// ---------------- K2: fused GEMM + argmax ----------------
// 256 threads as 16x16; thread (ty,tx) owns an 8x8 microtile of a 128x128
// (rows x codes) dot tile; iterates code tiles keeping per-row running best.
__global__ __launch_bounds__(256, 2)
void argmax_kernel(const float* __restrict__ x, const float* __restrict__ w,
                   int n, int ne) {
    __shared__ float xs[KB][BM];
    __shared__ float ws[KB][BE];
    __shared__ float sn[BE];
    __shared__ float rbest[BM][16];
    __shared__ int   rbind[BM][16];

    const int tid = threadIdx.x;
    const int tx = tid & 15, ty = tid >> 4;
    const int rowBase = blockIdx.x * BM;

    float best[8];
    int   bind[8];
    #pragma unroll
    for (int i = 0; i < 8; i++) { best[i] = -3.4e38f; bind[i] = 0; }

    const int nTiles = ne / BE;            // ne assumed multiple of 128
    for (int et = 0; et < nTiles; ++et) {
        __syncthreads();                   // protect sn from prev-iter readers
        if (tid < BE) sn[tid] = g_inv_norm[et * BE + tid];

        float acc[8][8];
        #pragma unroll
        for (int i = 0; i < 8; i++)
            #pragma unroll
            for (int j = 0; j < 8; j++) acc[i][j] = 0.f;

        for (int k0 = 0; k0 < DIM; k0 += KB) {
            __syncthreads();
            {
                const int r  = tid >> 2;   // 0..63
                const int kq = tid & 3;    // float4 slot within 16-wide k slab
                // clamp row indices so partial last tile never reads OOB
                int xr0 = rowBase + r;       if (xr0 >= n) xr0 = n - 1;
                int xr1 = rowBase + r + 64;  if (xr1 >= n) xr1 = n - 1;
                float4 v;
                v = *((const float4*)(x + (size_t)xr0 * DIM + k0) + kq);
                xs[kq*4+0][r] = v.x; xs[kq*4+1][r] = v.y;
                xs[kq*4+2][r] = v.z; xs[kq*4+3][r] = v.w;
                v = *((const float4*)(x + (size_t)xr1 * DIM + k0) + kq);
                xs[kq*4+0][r+64] = v.x; xs[kq*4+1][r+64] = v.y;
                xs[kq*4+2][r+64] = v.z; xs[kq*4+3][r+64] = v.w;
                v = *((const float4*)(w + (size_t)(et*BE + r) * DIM + k0) + kq);
                ws[kq*4+0][r] = v.x; ws[kq*4+1][r] = v.y;
                ws[kq*4+2][r] = v.z; ws[kq*4+3][r] = v.w;
                v = *((const float4*)(w + (size_t)(et*BE + r + 64) * DIM + k0) + kq);
                ws[kq*4+0][r+64] = v.x; ws[kq*4+1][r+64] = v.y;
                ws[kq*4+2][r+64] = v.z; ws[kq*4+3][r+64] = v.w;
            }
            __syncthreads();
            #pragma unroll
            for (int kk = 0; kk < KB; kk++) {
                float xa[8], wb[8];
                *(float4*)&xa[0] = *(const float4*)&xs[kk][ty*8];
                *(float4*)&xa[4] = *(const float4*)&xs[kk][ty*8 + 4];
                *(float4*)&wb[0] = *(const float4*)&ws[kk][tx*8];
                *(float4*)&wb[4] = *(const float4*)&ws[kk][tx*8 + 4];
                #pragma unroll
                for (int i = 0; i < 8; i++)
                    #pragma unroll
                    for (int j = 0; j < 8; j++)
                        acc[i][j] = fmaf(xa[i], wb[j], acc[i][j]);
            }
        }

        // fold tile into running argmax (codes ascending; strict > keeps
        // the first index on ties, matching jnp.argmin semantics)
        #pragma unroll
        for (int j = 0; j < 8; j++) {
            const float s  = sn[tx*8 + j];
            const int code = et*BE + tx*8 + j;
            #pragma unroll
            for (int i = 0; i < 8; i++) {
                float v = acc[i][j] * s;
                if (v > best[i]) { best[i] = v; bind[i] = code; }
            }
        }
    }

    #pragma unroll
    for (int i = 0; i < 8; i++) {
        rbest[ty*8 + i][tx] = best[i];
        rbind[ty*8 + i][tx] = bind[i];
    }
    __syncthreads();
    if (tid < BM && rowBase + tid < n) {
        float bv = rbest[tid][0];
        int   bi = rbind[tid][0];
        #pragma unroll
        for (int t = 1; t < 16; t++) {
            float v = rbest[tid][t];
            int  ii = rbind[tid][t];
            if (v > bv || (v == bv && ii < bi)) { bv = v; bi = ii; }
        }
        g_ind[rowBase + tid] = bi;
    }
}

// ---------------- K3: gather + MSE + index write ----------------
// one warp per x-row; block = 8 warps
__global__ void gather_kernel(const float* __restrict__ x,
                              const float* __restrict__ w,
                              float* __restrict__ out0,
                              float* __restrict__ out_ind,
                              int write_extra, int n) {
    const int warp = threadIdx.x >> 5, lane = threadIdx.x & 31;
    const int row  = blockIdx.x * 8 + warp;
    float lsum = 0.f;
    if (row < n) {
        const int ind  = g_ind[row];
        const float sc = g_scale[ind];
        const float4* px = (const float4*)(x + (size_t)row * DIM);
        const float4* pw = (const float4*)(w + (size_t)ind * DIM);
        float4* po = (float4*)(out0 + (size_t)row * DIM);
        #pragma unroll
        for (int it = 0; it < 4; ++it) {
            int idx = it * 32 + lane;
            float4 wv = pw[idx];
            float4 xv = px[idx];
            float4 q = make_float4(wv.x*sc, wv.y*sc, wv.z*sc, wv.w*sc);
            po[idx] = q;
            float dx = q.x - xv.x, dy = q.y - xv.y, dz = q.z - xv.z, dw = q.w - xv.w;
            lsum += dx*dx + dy*dy + dz*dz + dw*dw;
        }
        if (write_extra && lane == 0) out_ind[row] = (float)ind;
    }
    #pragma unroll
    for (int o = 16; o; o >>= 1) lsum += __shfl_down_sync(0xffffffffu, lsum, o);
    __shared__ float rs[8];
    if (lane == 0) rs[warp] = lsum;
    __syncthreads();
    if (threadIdx.x == 0) {
        float t = 0.f;
        #pragma unroll
        for (int i = 0; i < 8; i++) t += rs[i];
        atomicAdd(&g_diff, t);
    }
}

__global__ void finalize_kernel(float* __restrict__ diff_out, float inv_cnt) {
    *diff_out = g_diff * inv_cnt;
}

// ---------------- launch ----------------
extern "C" void kernel_launch(void* const* d_in, const int* in_sizes, int n_in,
                              void* d_out, int out_size) {
    const float* x = (const float*)d_in[0];
    const float* w = (const float*)d_in[1];
    int xs_elems = in_sizes[0], ws_elems = (n_in >= 2) ? in_sizes[1] : 0;
    // defensive input-order detection: weight is the smaller tensor
    if (n_in >= 2 && ws_elems > xs_elems) {
        const float* t = x; x = w; w = t;
        int te = xs_elems; xs_elems = ws_elems; ws_elems = te;
    }
    int n  = xs_elems / DIM;               // x rows
    int ne = ws_elems / DIM;               // codebook size
    if (n  > MAXN)  n  = MAXN;
    if (ne > MAXNE) ne = MAXNE;

    float* out = (float*)d_out;
    const long long full = (long long)n * DIM + 1 + n;
    const int write_extra = (out_size >= full);

    norms_kernel<<<ne, 128>>>(w, ne);
    argmax_kernel<<<(n + BM - 1) / BM, 256>>>(x, w, n, ne);
    gather_kernel<<<(n + 7) / 8, 256>>>(x, w, out,
                                        write_extra ? out + (size_t)n * DIM + 1 : out,
                                        write_extra, n);
    if (write_extra)
        finalize_kernel<<<1, 1>>>(out + (size_t)n * DIM,
                                  1.0f / ((float)n * (float)DIM));
}

// round 3
// speedup vs baseline: 1.0013x; 1.0013x over previous
#include <cuda_runtime.h>
#include <math.h>

#define DIM    512
#define MAXNE  4096
#define MAXN   65536

#define BM 128
#define BE 128
#define KB 16

// ---------------- device scratch (no allocs allowed) ----------------
__device__ float g_inv_norm[MAXNE];
__device__ float g_scale[MAXNE];
__device__ int   g_ind[MAXN];
__device__ float g_diff;

// ---------------- K1: per-code norms (+ reset g_diff) ----------------
__global__ void norms_kernel(const float* __restrict__ w, int ne) {
    int row = blockIdx.x;
    if (row >= ne) return;
    const float* wr = w + (size_t)row * DIM;
    float s = 0.f;
    for (int i = threadIdx.x; i < DIM; i += 128) {
        float v = wr[i];
        s += v * v;
    }
    __shared__ float red[4];
    #pragma unroll
    for (int o = 16; o; o >>= 1) s += __shfl_down_sync(0xffffffffu, s, o);
    if ((threadIdx.x & 31) == 0) red[threadIdx.x >> 5] = s;
    __syncthreads();
    if (threadIdx.x == 0) {
        float t = red[0] + red[1] + red[2] + red[3];
        float n = sqrtf(t);
        g_inv_norm[row] = 1.0f / n;
        g_scale[row]    = fminf(1.0f, 1.0f / fmaxf(n, 1e-7f));
        if (row == 0) g_diff = 0.f;        // ordered before gather (same stream)
    }
}

// ---------------- K2: fused GEMM + argmax ----------------
// 256 threads as 16x16; thread (ty,tx) owns an 8x8 microtile of a 128x128
// (rows x codes) dot tile; iterates code tiles keeping per-row running best.
__global__ __launch_bounds__(256, 2)
void argmax_kernel(const float* __restrict__ x, const float* __restrict__ w,
                   int n, int ne) {
    __shared__ float xs[KB][BM];
    __shared__ float ws[KB][BE];
    __shared__ float sn[BE];
    __shared__ float rbest[BM][16];
    __shared__ int   rbind[BM][16];

    const int tid = threadIdx.x;
    const int tx = tid & 15, ty = tid >> 4;
    const int rowBase = blockIdx.x * BM;

    float best[8];
    int   bind[8];
    #pragma unroll
    for (int i = 0; i < 8; i++) { best[i] = -3.4e38f; bind[i] = 0; }

    const int nTiles = ne / BE;            // ne assumed multiple of 128
    for (int et = 0; et < nTiles; ++et) {
        __syncthreads();                   // protect sn from prev-iter readers
        if (tid < BE) sn[tid] = g_inv_norm[et * BE + tid];

        float acc[8][8];
        #pragma unroll
        for (int i = 0; i < 8; i++)
            #pragma unroll
            for (int j = 0; j < 8; j++) acc[i][j] = 0.f;

        for (int k0 = 0; k0 < DIM; k0 += KB) {
            __syncthreads();
            {
                const int r  = tid >> 2;   // 0..63
                const int kq = tid & 3;    // float4 slot within 16-wide k slab
                // clamp row indices so partial last tile never reads OOB
                int xr0 = rowBase + r;       if (xr0 >= n) xr0 = n - 1;
                int xr1 = rowBase + r + 64;  if (xr1 >= n) xr1 = n - 1;
                float4 v;
                v = *((const float4*)(x + (size_t)xr0 * DIM + k0) + kq);
                xs[kq*4+0][r] = v.x; xs[kq*4+1][r] = v.y;
                xs[kq*4+2][r] = v.z; xs[kq*4+3][r] = v.w;
                v = *((const float4*)(x + (size_t)xr1 * DIM + k0) + kq);
                xs[kq*4+0][r+64] = v.x; xs[kq*4+1][r+64] = v.y;
                xs[kq*4+2][r+64] = v.z; xs[kq*4+3][r+64] = v.w;
                v = *((const float4*)(w + (size_t)(et*BE + r) * DIM + k0) + kq);
                ws[kq*4+0][r] = v.x; ws[kq*4+1][r] = v.y;
                ws[kq*4+2][r] = v.z; ws[kq*4+3][r] = v.w;
                v = *((const float4*)(w + (size_t)(et*BE + r + 64) * DIM + k0) + kq);
                ws[kq*4+0][r+64] = v.x; ws[kq*4+1][r+64] = v.y;
                ws[kq*4+2][r+64] = v.z; ws[kq*4+3][r+64] = v.w;
            }
            __syncthreads();
            #pragma unroll
            for (int kk = 0; kk < KB; kk++) {
                float xa[8], wb[8];
                *(float4*)&xa[0] = *(const float4*)&xs[kk][ty*8];
                *(float4*)&xa[4] = *(const float4*)&xs[kk][ty*8 + 4];
                *(float4*)&wb[0] = *(const float4*)&ws[kk][tx*8];
                *(float4*)&wb[4] = *(const float4*)&ws[kk][tx*8 + 4];
                #pragma unroll
                for (int i = 0; i < 8; i++)
                    #pragma unroll
                    for (int j = 0; j < 8; j++)
                        acc[i][j] = fmaf(xa[i], wb[j], acc[i][j]);
            }
        }

        // fold tile into running argmax (codes ascending; strict > keeps
        // the first index on ties, matching jnp.argmin semantics)
        #pragma unroll
        for (int j = 0; j < 8; j++) {
            const float s  = sn[tx*8 + j];
            const int code = et*BE + tx*8 + j;
            #pragma unroll
            for (int i = 0; i < 8; i++) {
                float v = acc[i][j] * s;
                if (v > best[i]) { best[i] = v; bind[i] = code; }
            }
        }
    }

    #pragma unroll
    for (int i = 0; i < 8; i++) {
        rbest[ty*8 + i][tx] = best[i];
        rbind[ty*8 + i][tx] = bind[i];
    }
    __syncthreads();
    if (tid < BM && rowBase + tid < n) {
        float bv = rbest[tid][0];
        int   bi = rbind[tid][0];
        #pragma unroll
        for (int t = 1; t < 16; t++) {
            float v = rbest[tid][t];
            int  ii = rbind[tid][t];
            if (v > bv || (v == bv && ii < bi)) { bv = v; bi = ii; }
        }
        g_ind[rowBase + tid] = bi;
    }
}

// ---------------- K3: gather + MSE + index write ----------------
// one warp per x-row; block = 8 warps
__global__ void gather_kernel(const float* __restrict__ x,
                              const float* __restrict__ w,
                              float* __restrict__ out0,
                              float* __restrict__ out_ind,
                              int write_extra, int n) {
    const int warp = threadIdx.x >> 5, lane = threadIdx.x & 31;
    const int row  = blockIdx.x * 8 + warp;
    float lsum = 0.f;
    if (row < n) {
        const int ind  = g_ind[row];
        const float sc = g_scale[ind];
        const float4* px = (const float4*)(x + (size_t)row * DIM);
        const float4* pw = (const float4*)(w + (size_t)ind * DIM);
        float4* po = (float4*)(out0 + (size_t)row * DIM);
        #pragma unroll
        for (int it = 0; it < 4; ++it) {
            int idx = it * 32 + lane;
            float4 wv = pw[idx];
            float4 xv = px[idx];
            float4 q = make_float4(wv.x*sc, wv.y*sc, wv.z*sc, wv.w*sc);
            po[idx] = q;
            float dx = q.x - xv.x, dy = q.y - xv.y, dz = q.z - xv.z, dw = q.w - xv.w;
            lsum += dx*dx + dy*dy + dz*dz + dw*dw;
        }
        if (write_extra && lane == 0) out_ind[row] = (float)ind;
    }
    #pragma unroll
    for (int o = 16; o; o >>= 1) lsum += __shfl_down_sync(0xffffffffu, lsum, o);
    __shared__ float rs[8];
    if (lane == 0) rs[warp] = lsum;
    __syncthreads();
    if (threadIdx.x == 0) {
        float t = 0.f;
        #pragma unroll
        for (int i = 0; i < 8; i++) t += rs[i];
        atomicAdd(&g_diff, t);
    }
}

__global__ void finalize_kernel(float* __restrict__ diff_out, float inv_cnt) {
    *diff_out = g_diff * inv_cnt;
}

// ---------------- launch ----------------
extern "C" void kernel_launch(void* const* d_in, const int* in_sizes, int n_in,
                              void* d_out, int out_size) {
    const float* x = (const float*)d_in[0];
    const float* w = (const float*)d_in[1];
    int xs_elems = in_sizes[0], ws_elems = (n_in >= 2) ? in_sizes[1] : 0;
    // defensive input-order detection: weight is the smaller tensor
    if (n_in >= 2 && ws_elems > xs_elems) {
        const float* t = x; x = w; w = t;
        int te = xs_elems; xs_elems = ws_elems; ws_elems = te;
    }
    int n  = xs_elems / DIM;               // x rows
    int ne = ws_elems / DIM;               // codebook size
    if (n  > MAXN)  n  = MAXN;
    if (ne > MAXNE) ne = MAXNE;

    float* out = (float*)d_out;
    const long long full = (long long)n * DIM + 1 + n;
    const int write_extra = (out_size >= full);

    norms_kernel<<<ne, 128>>>(w, ne);
    argmax_kernel<<<(n + BM - 1) / BM, 256>>>(x, w, n, ne);
    gather_kernel<<<(n + 7) / 8, 256>>>(x, w, out,
                                        write_extra ? out + (size_t)n * DIM + 1 : out,
                                        write_extra, n);
    if (write_extra)
        finalize_kernel<<<1, 1>>>(out + (size_t)n * DIM,
                                  1.0f / ((float)n * (float)DIM));
}

// round 8
// speedup vs baseline: 2.1882x; 2.1854x over previous
#include <cuda_runtime.h>
#include <cuda_fp16.h>
#include <math.h>
#include <stdint.h>

#define DIM    512
#define MAXN   32768
#define MAXNE  4096
#define MARGIN 4e-3f
#define BM 128

// small scratch only (~550 KB total — matches the footprint that passed R2/R3)
__device__ float g_inv_norm[MAXNE];
__device__ float g_scale[MAXNE];
__device__ int   g_ind[MAXN];
__device__ float g_diff;
__device__ int   g_nflag;
__device__ int   g_flag[MAXN];
__device__ unsigned long long g_best[MAXN];

__device__ __forceinline__ uint32_t smem_u32(const void* p) {
    uint32_t a;
    asm("{ .reg .u64 t; cvta.to.shared.u64 t, %1; cvt.u32.u64 %0, t; }" : "=r"(a) : "l"(p));
    return a;
}
__device__ __forceinline__ void cpa16(uint32_t dst, const void* src) {
    asm volatile("cp.async.cg.shared.global [%0], [%1], 16;" :: "r"(dst), "l"(src) : "memory");
}
#define CPC()  asm volatile("cp.async.commit_group;" ::: "memory")
#define CPW(n) asm volatile("cp.async.wait_group %0;" :: "n"(n) : "memory")

__device__ __forceinline__ void ldsm4(uint32_t& a0, uint32_t& a1, uint32_t& a2, uint32_t& a3, uint32_t addr) {
    asm volatile("ldmatrix.sync.aligned.m8n8.x4.shared.b16 {%0,%1,%2,%3}, [%4];"
                 : "=r"(a0), "=r"(a1), "=r"(a2), "=r"(a3) : "r"(addr));
}
__device__ __forceinline__ void mma16816(float* c, const uint32_t* a, const uint32_t* b) {
    asm volatile("mma.sync.aligned.m16n8k16.row.col.f32.f16.f16.f32 "
                 "{%0,%1,%2,%3}, {%4,%5,%6,%7}, {%8,%9}, {%0,%1,%2,%3};"
                 : "+f"(c[0]), "+f"(c[1]), "+f"(c[2]), "+f"(c[3])
                 : "r"(a[0]), "r"(a[1]), "r"(a[2]), "r"(a[3]), "r"(b[0]), "r"(b[1]));
}
__device__ __forceinline__ void upd(float& b, float& s, int& i, float v, int col) {
    if (v > b) { s = b; b = v; i = col; } else if (v > s) s = v;
}
__device__ __forceinline__ void mrg(float& b, float& s, int& i, float ob, float os, int oi) {
    if (ob > b || (ob == b && oi < i)) { s = fmaxf(b, os); b = ob; i = oi; }
    else s = fmaxf(s, ob);
}

// ---- K1: norms + resets ----
__global__ void norms_kernel(const float* __restrict__ w, int ne) {
    int row = blockIdx.x;
    const float* wr = w + (size_t)row * DIM;
    float s = 0.f;
    for (int i = threadIdx.x; i < DIM; i += 128) { float v = wr[i]; s += v * v; }
    __shared__ float red[4];
    #pragma unroll
    for (int o = 16; o; o >>= 1) s += __shfl_down_sync(0xffffffffu, s, o);
    if ((threadIdx.x & 31) == 0) red[threadIdx.x >> 5] = s;
    __syncthreads();
    if (threadIdx.x == 0) {
        float t = red[0] + red[1] + red[2] + red[3];
        float nm = sqrtf(t);
        g_inv_norm[row] = 1.0f / nm;
        g_scale[row] = fminf(1.0f, 1.0f / fmaxf(nm, 1e-7f));
        if (row == 0) { g_diff = 0.f; g_nflag = 0; }
    }
}

// ---- K2: fp32 -> fp16 (into d_out scratch) ----
__global__ void tohalf_kernel(const float* __restrict__ src, __half* __restrict__ dst, int n4) {
    int i = blockIdx.x * blockDim.x + threadIdx.x;
    if (i >= n4) return;
    float4 v = ((const float4*)src)[i];
    ((__half2*)dst)[i * 2]     = __floats2half2_rn(v.x, v.y);
    ((__half2*)dst)[i * 2 + 1] = __floats2half2_rn(v.z, v.w);
}

// ---- K3: fp16 tensor-core GEMM + fused top-2 argmax ----
// 256 thr = 8 warps (2M x 4N); CTA tile 128x128; warp tile 64x32.
// K=512 in 8 blocks of 64 halves (128B rows), 3-stage cp.async pipeline (96KB).
__global__ __launch_bounds__(256, 1)
void gemm_argmax(const __half* __restrict__ xh, const __half* __restrict__ wh,
                 int n, int ne) {
    extern __shared__ char sm[];
    const uint32_t sb = smem_u32(sm);
    const int tid = threadIdx.x, lane = tid & 31, wid = tid >> 5;
    const int wm = wid >> 2, wn = wid & 3;
    const int rowBase = blockIdx.x * BM;
    const int tiles = ne >> 7;

    float best[8], second[8];
    int bidx[8];
    #pragma unroll
    for (int s = 0; s < 8; ++s) { best[s] = -3.4e38f; second[s] = -3.4e38f; bidx[s] = 0; }

    for (int ct = 0; ct < tiles; ++ct) {
        float acc[4][4][4];
        #pragma unroll
        for (int mt = 0; mt < 4; ++mt)
            #pragma unroll
            for (int nt = 0; nt < 4; ++nt)
                #pragma unroll
                for (int k = 0; k < 4; ++k) acc[mt][nt][k] = 0.f;

        #pragma unroll
        for (int pb = 0; pb < 2; ++pb) {
            #pragma unroll
            for (int i = 0; i < 4; ++i) {
                int idx = tid + i * 256;            // 0..1023
                int r = idx >> 3, c = idx & 7;
                uint32_t sw = (uint32_t)(r * 128) + (uint32_t)((c ^ (r & 7)) << 4);
                int gr = rowBase + r; if (gr >= n) gr = n - 1;
                cpa16(sb + pb * 32768 + sw, xh + (size_t)gr * DIM + pb * 64 + c * 8);
                cpa16(sb + pb * 32768 + 16384 + sw, wh + (size_t)(ct * 128 + r) * DIM + pb * 64 + c * 8);
            }
            CPC();
        }

        for (int kb = 0; kb < 8; ++kb) {
            if (kb < 6) { CPW(1); } else { CPW(0); }
            __syncthreads();
            const uint32_t ab = sb + (kb % 3) * 32768;
            const uint32_t bb = ab + 16384;
            #pragma unroll
            for (int ks = 0; ks < 4; ++ks) {
                uint32_t a[4][4];
                #pragma unroll
                for (int mt = 0; mt < 4; ++mt) {
                    int ar = wm * 64 + mt * 16 + (lane & 15);
                    int kc = ks * 2 + (lane >> 4);
                    ldsm4(a[mt][0], a[mt][1], a[mt][2], a[mt][3],
                          ab + ar * 128 + ((kc ^ (ar & 7)) << 4));
                }
                uint32_t bq[2][4];
                #pragma unroll
                for (int p = 0; p < 2; ++p) {
                    int br = wn * 32 + p * 16 + (lane & 7) + ((lane >> 4) << 3);
                    int kc = ks * 2 + ((lane >> 3) & 1);
                    ldsm4(bq[p][0], bq[p][1], bq[p][2], bq[p][3],
                          bb + br * 128 + ((kc ^ (br & 7)) << 4));
                }
                #pragma unroll
                for (int mt = 0; mt < 4; ++mt)
                    #pragma unroll
                    for (int nt = 0; nt < 4; ++nt)
                        mma16816(acc[mt][nt], a[mt], &bq[nt >> 1][(nt & 1) * 2]);
            }
            __syncthreads();
            if (kb + 2 < 8) {
                int s = (kb + 2) % 3;
                #pragma unroll
                for (int i = 0; i < 4; ++i) {
                    int idx = tid + i * 256;
                    int r = idx >> 3, c = idx & 7;
                    uint32_t sw = (uint32_t)(r * 128) + (uint32_t)((c ^ (r & 7)) << 4);
                    int gr = rowBase + r; if (gr >= n) gr = n - 1;
                    cpa16(sb + s * 32768 + sw, xh + (size_t)gr * DIM + (kb + 2) * 64 + c * 8);
                    cpa16(sb + s * 32768 + 16384 + sw, wh + (size_t)(ct * 128 + r) * DIM + (kb + 2) * 64 + c * 8);
                }
                CPC();
            }
        }

        // fold 128-code tile into running top-2 (codes ascend -> first-index ties)
        #pragma unroll
        for (int nt = 0; nt < 4; ++nt) {
            int col = ct * 128 + wn * 32 + nt * 8 + (lane & 3) * 2;
            float i0 = __ldg(&g_inv_norm[col]);
            float i1 = __ldg(&g_inv_norm[col + 1]);
            #pragma unroll
            for (int mt = 0; mt < 4; ++mt) {
                int s0 = mt * 2, s1 = mt * 2 + 1;
                upd(best[s0], second[s0], bidx[s0], acc[mt][nt][0] * i0, col);
                upd(best[s0], second[s0], bidx[s0], acc[mt][nt][1] * i1, col + 1);
                upd(best[s1], second[s1], bidx[s1], acc[mt][nt][2] * i0, col);
                upd(best[s1], second[s1], bidx[s1], acc[mt][nt][3] * i1, col + 1);
            }
        }
    }

    // lane merge within row-quads
    #pragma unroll
    for (int s = 0; s < 8; ++s) {
        #pragma unroll
        for (int d = 1; d <= 2; d <<= 1) {
            float ob = __shfl_xor_sync(0xffffffffu, best[s], d);
            float os = __shfl_xor_sync(0xffffffffu, second[s], d);
            int   oi = __shfl_xor_sync(0xffffffffu, bidx[s], d);
            mrg(best[s], second[s], bidx[s], ob, os, oi);
        }
    }

    // cross-warp (wn) merge via smem: [4][128]
    __syncthreads();
    float* mb = (float*)sm;
    float* ms = mb + 512;
    int*   mi = (int*)(ms + 512);
    if ((lane & 3) == 0) {
        #pragma unroll
        for (int s = 0; s < 8; ++s) {
            int row = wm * 64 + (s >> 1) * 16 + (s & 1) * 8 + (lane >> 2);
            mb[wn * 128 + row] = best[s];
            ms[wn * 128 + row] = second[s];
            mi[wn * 128 + row] = bidx[s];
        }
    }
    __syncthreads();
    if (tid < 128) {
        float bb2 = mb[tid], ss2 = ms[tid];
        int bi = mi[tid];
        #pragma unroll
        for (int w = 1; w < 4; ++w)
            mrg(bb2, ss2, bi, mb[w * 128 + tid], ms[w * 128 + tid], mi[w * 128 + tid]);
        int grow = rowBase + tid;
        if (grow < n) {
            g_ind[grow] = bi;
            if (bb2 - ss2 < MARGIN) {
                int pos = atomicAdd(&g_nflag, 1);
                if (pos < MAXN) g_flag[pos] = grow;
                g_best[grow] = 0ull;
            }
        }
    }
}

// ---- K4: exact fp32 recheck (all register indices static) ----
__global__ __launch_bounds__(256, 1)
void recheck_kernel(const float* __restrict__ x, const float* __restrict__ w, int ne) {
    __shared__ float xs[8][DIM];
    const int tid = threadIdx.x, warp = tid >> 5, lane = tid & 31;
    int nf = g_nflag; if (nf > MAXN) nf = MAXN;
    for (int base = blockIdx.x * 8; base < nf; base += gridDim.x * 8) {
        int cnt = nf - base; if (cnt > 8) cnt = 8;
        __syncthreads();
        for (int e = tid; e < cnt * DIM; e += 256) {
            int r = e >> 9, k = e & 511;
            xs[r][k] = x[(size_t)g_flag[base + r] * DIM + k];
        }
        __syncthreads();
        for (int j = warp; j < ne; j += 8) {
            const float4* wj = (const float4*)(w + (size_t)j * DIM);
            float acc[8];
            #pragma unroll
            for (int r = 0; r < 8; ++r) acc[r] = 0.f;
            #pragma unroll
            for (int qq = 0; qq < 4; ++qq) {
                int q = lane + qq * 32;
                float4 wv = __ldg(wj + q);
                #pragma unroll
                for (int r = 0; r < 8; ++r) {
                    if (r < cnt) {
                        float4 xv = *(const float4*)&xs[r][q * 4];
                        acc[r] = fmaf(xv.x, wv.x, fmaf(xv.y, wv.y, fmaf(xv.z, wv.z, fmaf(xv.w, wv.w, acc[r]))));
                    }
                }
            }
            float inv = g_inv_norm[j];
            #pragma unroll
            for (int r = 0; r < 8; ++r) {
                if (r < cnt) {
                    float v = acc[r];
                    #pragma unroll
                    for (int o = 16; o; o >>= 1) v += __shfl_down_sync(0xffffffffu, v, o);
                    if (lane == 0) {
                        float m = v * inv;
                        uint32_t u = __float_as_uint(m);
                        u = (u & 0x80000000u) ? ~u : (u | 0x80000000u);
                        unsigned long long key = ((unsigned long long)u << 32) | (0xFFFFFFFFu - (uint32_t)j);
                        atomicMax(&g_best[g_flag[base + r]], key);
                    }
                }
            }
        }
    }
}

__global__ void fix_kernel() {
    int nf = g_nflag; if (nf > MAXN) nf = MAXN;
    for (int i = threadIdx.x; i < nf; i += 256) {
        int row = g_flag[i];
        g_ind[row] = (int)(0xFFFFFFFFu - (uint32_t)(g_best[row] & 0xFFFFFFFFull));
    }
}

// ---- K5: gather + MSE (overwrites the scratch region with real output) ----
__global__ void gather_kernel(const float* __restrict__ x, const float* __restrict__ w,
                              float* __restrict__ out0, float* __restrict__ out_ind,
                              int write_extra, int n) {
    const int warp = threadIdx.x >> 5, lane = threadIdx.x & 31;
    const int row = blockIdx.x * 8 + warp;
    float lsum = 0.f;
    if (row < n) {
        const int ind = g_ind[row];
        const float sc = g_scale[ind];
        const float4* px = (const float4*)(x + (size_t)row * DIM);
        const float4* pw = (const float4*)(w + (size_t)ind * DIM);
        float4* po = (float4*)(out0 + (size_t)row * DIM);
        #pragma unroll
        for (int it = 0; it < 4; ++it) {
            int idx = it * 32 + lane;
            float4 wv = pw[idx], xv = px[idx];
            float4 q = make_float4(wv.x * sc, wv.y * sc, wv.z * sc, wv.w * sc);
            po[idx] = q;
            float dx = q.x - xv.x, dy = q.y - xv.y, dz = q.z - xv.z, dw = q.w - xv.w;
            lsum += dx * dx + dy * dy + dz * dz + dw * dw;
        }
        if (write_extra && lane == 0) out_ind[row] = (float)ind;
    }
    #pragma unroll
    for (int o = 16; o; o >>= 1) lsum += __shfl_down_sync(0xffffffffu, lsum, o);
    __shared__ float rs[8];
    if (lane == 0) rs[warp] = lsum;
    __syncthreads();
    if (threadIdx.x == 0) {
        float tt = 0.f;
        #pragma unroll
        for (int i = 0; i < 8; i++) tt += rs[i];
        atomicAdd(&g_diff, tt);
    }
}

__global__ void finalize_kernel(float* __restrict__ diff_out, float inv_cnt) {
    *diff_out = g_diff * inv_cnt;
}

// ---- launch ----
extern "C" void kernel_launch(void* const* d_in, const int* in_sizes, int n_in,
                              void* d_out, int out_size) {
    const float* x = (const float*)d_in[0];
    const float* w = (const float*)d_in[1];
    int xe = in_sizes[0], we = (n_in >= 2) ? in_sizes[1] : 0;
    if (n_in >= 2 && we > xe) { const float* t = x; x = w; w = t; int te = xe; xe = we; we = te; }
    int n = xe / DIM, ne = we / DIM;
    if (n > MAXN) n = MAXN;
    if (ne > MAXNE) ne = MAXNE;
    float* out = (float*)d_out;
    const long long full = (long long)n * DIM + 1 + n;
    const int write_extra = (out_size >= full);

    // fp16 scratch inside d_out's first region (overwritten by gather later):
    //   xh: n*DIM halves at float-offset 0
    //   wh: ne*DIM halves at float-offset n*DIM/2
    __half* xh = (__half*)out;
    __half* wh = (__half*)(out + (size_t)n * DIM / 2);

    cudaFuncSetAttribute(gemm_argmax, cudaFuncAttributeMaxDynamicSharedMemorySize, 98304);

    norms_kernel<<<ne, 128>>>(w, ne);
    tohalf_kernel<<<(ne * DIM / 4 + 255) / 256, 256>>>(w, wh, ne * DIM / 4);
    tohalf_kernel<<<(n * DIM / 4 + 255) / 256, 256>>>(x, xh, n * DIM / 4);
    gemm_argmax<<<(n + BM - 1) / BM, 256, 98304>>>(xh, wh, n, ne);
    recheck_kernel<<<148, 256>>>(x, w, ne);
    fix_kernel<<<1, 256>>>();
    gather_kernel<<<(n + 7) / 8, 256>>>(x, w, out,
                                        write_extra ? out + (size_t)n * DIM + 1 : out,
                                        write_extra, n);
    if (write_extra)
        finalize_kernel<<<1, 1>>>(out + (size_t)n * DIM, 1.0f / ((float)n * (float)DIM));
}

// round 10
// speedup vs baseline: 2.2852x; 1.0443x over previous
#include <cuda_runtime.h>
#include <cuda_fp16.h>
#include <math.h>
#include <stdint.h>

#define DIM    512
#define MAXN   32768
#define MAXNE  4096
#define MARGIN 4e-3f
#define BM 128

// small scratch only (~680 KB)
__device__ float g_inv_norm[MAXNE];
__device__ float g_scale[MAXNE];
__device__ int   g_ind[MAXN];
__device__ int   g_flag01[MAXN];
__device__ float g_diff;
__device__ int   g_nflag;
__device__ int   g_flag[MAXN];
__device__ unsigned long long g_best[MAXN];

__device__ __forceinline__ uint32_t smem_u32(const void* p) {
    uint32_t a;
    asm("{ .reg .u64 t; cvta.to.shared.u64 t, %1; cvt.u32.u64 %0, t; }" : "=r"(a) : "l"(p));
    return a;
}
__device__ __forceinline__ void cpa16(uint32_t dst, const void* src) {
    asm volatile("cp.async.cg.shared.global [%0], [%1], 16;" :: "r"(dst), "l"(src) : "memory");
}
#define CPC()  asm volatile("cp.async.commit_group;" ::: "memory")
#define CPW(n) asm volatile("cp.async.wait_group %0;" :: "n"(n) : "memory")

__device__ __forceinline__ void ldsm4(uint32_t& a0, uint32_t& a1, uint32_t& a2, uint32_t& a3, uint32_t addr) {
    asm volatile("ldmatrix.sync.aligned.m8n8.x4.shared.b16 {%0,%1,%2,%3}, [%4];"
                 : "=r"(a0), "=r"(a1), "=r"(a2), "=r"(a3) : "r"(addr));
}
__device__ __forceinline__ void mma16816(float* c, const uint32_t* a, const uint32_t* b) {
    asm volatile("mma.sync.aligned.m16n8k16.row.col.f32.f16.f16.f32 "
                 "{%0,%1,%2,%3}, {%4,%5,%6,%7}, {%8,%9}, {%0,%1,%2,%3};"
                 : "+f"(c[0]), "+f"(c[1]), "+f"(c[2]), "+f"(c[3])
                 : "r"(a[0]), "r"(a[1]), "r"(a[2]), "r"(a[3]), "r"(b[0]), "r"(b[1]));
}
__device__ __forceinline__ void upd(float& b, float& s, int& i, float v, int col) {
    if (v > b) { s = b; b = v; i = col; } else if (v > s) s = v;
}
__device__ __forceinline__ void mrg(float& b, float& s, int& i, float ob, float os, int oi) {
    if (ob > b || (ob == b && oi < i)) { s = fmaxf(b, os); b = ob; i = oi; }
    else s = fmaxf(s, ob);
}

// ---- K1: fused norms + w fp16 conversion + resets ----
__global__ void prep_w(const float* __restrict__ w, __half* __restrict__ wh, int ne) {
    int row = blockIdx.x;
    const float* wr = w + (size_t)row * DIM;
    float4 v = ((const float4*)wr)[threadIdx.x];
    float s = v.x*v.x + v.y*v.y + v.z*v.z + v.w*v.w;
    ((__half2*)(wh + (size_t)row * DIM))[threadIdx.x * 2]     = __floats2half2_rn(v.x, v.y);
    ((__half2*)(wh + (size_t)row * DIM))[threadIdx.x * 2 + 1] = __floats2half2_rn(v.z, v.w);
    __shared__ float red[4];
    #pragma unroll
    for (int o = 16; o; o >>= 1) s += __shfl_down_sync(0xffffffffu, s, o);
    if ((threadIdx.x & 31) == 0) red[threadIdx.x >> 5] = s;
    __syncthreads();
    if (threadIdx.x == 0) {
        float t = red[0] + red[1] + red[2] + red[3];
        float nm = sqrtf(t);
        g_inv_norm[row] = 1.0f / nm;
        g_scale[row] = fminf(1.0f, 1.0f / fmaxf(nm, 1e-7f));
        if (row == 0) { g_diff = 0.f; g_nflag = 0; }
    }
}

// ---- K2: fp32 -> fp16 for x (into d_out scratch) ----
__global__ void tohalf_kernel(const float* __restrict__ src, __half* __restrict__ dst, int n4) {
    int i = blockIdx.x * blockDim.x + threadIdx.x;
    if (i >= n4) return;
    float4 v = ((const float4*)src)[i];
    ((__half2*)dst)[i * 2]     = __floats2half2_rn(v.x, v.y);
    ((__half2*)dst)[i * 2 + 1] = __floats2half2_rn(v.z, v.w);
}

// ---- K3: fp16 HMMA GEMM + fused top-2 argmax, flat chunk pipeline ----
// 256 thr = 8 warps (2M x 4N), CTA tile 128x128, warp tile 64x32.
// Chunk = K=128 halves: stage 64KB (A 32KB + B 32KB), 3 stages = 192KB.
// ONE barrier per chunk; prefetch crosses code-tile boundaries (no drains).
__global__ __launch_bounds__(256, 1)
void gemm_argmax(const __half* __restrict__ xh, const __half* __restrict__ wh,
                 int n, int ne) {
    extern __shared__ char sm[];
    const uint32_t sb = smem_u32(sm);
    const int tid = threadIdx.x, lane = tid & 31, wid = tid >> 5;
    const int wm = wid >> 2, wn = wid & 3;
    const int rowBase = blockIdx.x * BM;
    const int tiles = ne >> 7;
    const int nchunks = tiles * 4;          // 4 chunks of K=128 per code tile

    auto issue = [&](int h, int st) {
        const int ctb = h >> 2, kb = h & 3;
        #pragma unroll
        for (int i = 0; i < 8; ++i) {
            int idx = tid + i * 256;         // 0..2047
            int sub = idx >> 10;             // 64-half sub-block 0/1
            int rem = idx & 1023;
            int r = rem >> 3, c = rem & 7;
            uint32_t sw = (uint32_t)(sub * 16384 + r * 128 + ((c ^ (r & 7)) << 4));
            int gr = rowBase + r; if (gr >= n) gr = n - 1;
            cpa16(sb + st * 65536 + sw,
                  xh + (size_t)gr * DIM + kb * 128 + sub * 64 + c * 8);
            cpa16(sb + st * 65536 + 32768 + sw,
                  wh + (size_t)(ctb * 128 + r) * DIM + kb * 128 + sub * 64 + c * 8);
        }
        CPC();
    };

    float best[8], second[8];
    int bidx[8];
    #pragma unroll
    for (int s = 0; s < 8; ++s) { best[s] = -3.4e38f; second[s] = -3.4e38f; bidx[s] = 0; }

    float acc[4][4][4];
    #pragma unroll
    for (int mt = 0; mt < 4; ++mt)
        #pragma unroll
        for (int nt = 0; nt < 4; ++nt)
            #pragma unroll
            for (int k = 0; k < 4; ++k) acc[mt][nt][k] = 0.f;

    issue(0, 0);
    issue(1, 1);

    for (int g = 0; g < nchunks; ++g) {
        if (g == nchunks - 1) { CPW(0); } else { CPW(1); }
        __syncthreads();
        if (g + 2 < nchunks) issue(g + 2, (g + 2) % 3);

        const uint32_t ab = sb + (g % 3) * 65536;
        const uint32_t bb = ab + 32768;
        #pragma unroll
        for (int ks = 0; ks < 8; ++ks) {
            const int sub = ks >> 2, ksl = ks & 3;
            const uint32_t abase = ab + sub * 16384;
            const uint32_t bbase = bb + sub * 16384;
            uint32_t a[4][4];
            #pragma unroll
            for (int mt = 0; mt < 4; ++mt) {
                int ar = wm * 64 + mt * 16 + (lane & 15);
                int kc = ksl * 2 + (lane >> 4);
                ldsm4(a[mt][0], a[mt][1], a[mt][2], a[mt][3],
                      abase + ar * 128 + ((kc ^ (ar & 7)) << 4));
            }
            uint32_t bq[2][4];
            #pragma unroll
            for (int p = 0; p < 2; ++p) {
                int br = wn * 32 + p * 16 + (lane & 7) + ((lane >> 4) << 3);
                int kc = ksl * 2 + ((lane >> 3) & 1);
                ldsm4(bq[p][0], bq[p][1], bq[p][2], bq[p][3],
                      bbase + br * 128 + ((kc ^ (br & 7)) << 4));
            }
            #pragma unroll
            for (int mt = 0; mt < 4; ++mt)
                #pragma unroll
                for (int nt = 0; nt < 4; ++nt)
                    mma16816(acc[mt][nt], a[mt], &bq[nt >> 1][(nt & 1) * 2]);
        }

        if ((g & 3) == 3) {                 // fold finished code tile, reset acc
            const int ct = g >> 2;
            #pragma unroll
            for (int nt = 0; nt < 4; ++nt) {
                int col = ct * 128 + wn * 32 + nt * 8 + (lane & 3) * 2;
                float i0 = __ldg(&g_inv_norm[col]);
                float i1 = __ldg(&g_inv_norm[col + 1]);
                #pragma unroll
                for (int mt = 0; mt < 4; ++mt) {
                    int s0 = mt * 2, s1 = mt * 2 + 1;
                    upd(best[s0], second[s0], bidx[s0], acc[mt][nt][0] * i0, col);
                    upd(best[s0], second[s0], bidx[s0], acc[mt][nt][1] * i1, col + 1);
                    upd(best[s1], second[s1], bidx[s1], acc[mt][nt][2] * i0, col);
                    upd(best[s1], second[s1], bidx[s1], acc[mt][nt][3] * i1, col + 1);
                    acc[mt][nt][0] = 0.f; acc[mt][nt][1] = 0.f;
                    acc[mt][nt][2] = 0.f; acc[mt][nt][3] = 0.f;
                }
            }
        }
    }

    // lane merge within row-quads
    #pragma unroll
    for (int s = 0; s < 8; ++s) {
        #pragma unroll
        for (int d = 1; d <= 2; d <<= 1) {
            float ob = __shfl_xor_sync(0xffffffffu, best[s], d);
            float os = __shfl_xor_sync(0xffffffffu, second[s], d);
            int   oi = __shfl_xor_sync(0xffffffffu, bidx[s], d);
            mrg(best[s], second[s], bidx[s], ob, os, oi);
        }
    }

    // cross-warp merge via smem (stages already drained)
    __syncthreads();
    float* mb = (float*)sm;
    float* ms = mb + 512;
    int*   mi = (int*)(ms + 512);
    if ((lane & 3) == 0) {
        #pragma unroll
        for (int s = 0; s < 8; ++s) {
            int row = wm * 64 + (s >> 1) * 16 + (s & 1) * 8 + (lane >> 2);
            mb[wn * 128 + row] = best[s];
            ms[wn * 128 + row] = second[s];
            mi[wn * 128 + row] = bidx[s];
        }
    }
    __syncthreads();
    if (tid < 128) {
        float bb2 = mb[tid], ss2 = ms[tid];
        int bi = mi[tid];
        #pragma unroll
        for (int w = 1; w < 4; ++w)
            mrg(bb2, ss2, bi, mb[w * 128 + tid], ms[w * 128 + tid], mi[w * 128 + tid]);
        int grow = rowBase + tid;
        if (grow < n) {
            g_ind[grow] = bi;
            int fl = (bb2 - ss2 < MARGIN) ? 1 : 0;
            g_flag01[grow] = fl;
            if (fl) {
                int pos = atomicAdd(&g_nflag, 1);
                if (pos < MAXN) g_flag[pos] = grow;
                g_best[grow] = 0ull;
            }
        }
    }
}

// ---- K4: exact fp32 recheck of flagged rows ----
__global__ __launch_bounds__(256, 1)
void recheck_kernel(const float* __restrict__ x, const float* __restrict__ w, int ne) {
    __shared__ float xs[8][DIM];
    const int tid = threadIdx.x, warp = tid >> 5, lane = tid & 31;
    int nf = g_nflag; if (nf > MAXN) nf = MAXN;
    for (int base = blockIdx.x * 8; base < nf; base += gridDim.x * 8) {
        int cnt = nf - base; if (cnt > 8) cnt = 8;
        __syncthreads();
        for (int e = tid; e < cnt * DIM; e += 256) {
            int r = e >> 9, k = e & 511;
            xs[r][k] = x[(size_t)g_flag[base + r] * DIM + k];
        }
        __syncthreads();
        for (int j = warp; j < ne; j += 8) {
            const float4* wj = (const float4*)(w + (size_t)j * DIM);
            float acc[8];
            #pragma unroll
            for (int r = 0; r < 8; ++r) acc[r] = 0.f;
            #pragma unroll
            for (int qq = 0; qq < 4; ++qq) {
                int q = lane + qq * 32;
                float4 wv = __ldg(wj + q);
                #pragma unroll
                for (int r = 0; r < 8; ++r) {
                    if (r < cnt) {
                        float4 xv = *(const float4*)&xs[r][q * 4];
                        acc[r] = fmaf(xv.x, wv.x, fmaf(xv.y, wv.y, fmaf(xv.z, wv.z, fmaf(xv.w, wv.w, acc[r]))));
                    }
                }
            }
            float inv = g_inv_norm[j];
            #pragma unroll
            for (int r = 0; r < 8; ++r) {
                if (r < cnt) {
                    float v = acc[r];
                    #pragma unroll
                    for (int o = 16; o; o >>= 1) v += __shfl_down_sync(0xffffffffu, v, o);
                    if (lane == 0) {
                        float m = v * inv;
                        uint32_t u = __float_as_uint(m);
                        u = (u & 0x80000000u) ? ~u : (u | 0x80000000u);
                        unsigned long long key = ((unsigned long long)u << 32) | (0xFFFFFFFFu - (uint32_t)j);
                        atomicMax(&g_best[g_flag[base + r]], key);
                    }
                }
            }
        }
    }
}

// ---- K5: gather + MSE (+ inline fix of flagged rows) ----
__global__ void gather_kernel(const float* __restrict__ x, const float* __restrict__ w,
                              float* __restrict__ out0, float* __restrict__ out_ind,
                              int write_extra, int n) {
    const int warp = threadIdx.x >> 5, lane = threadIdx.x & 31;
    const int row = blockIdx.x * 8 + warp;
    float lsum = 0.f;
    if (row < n) {
        int ind = g_ind[row];
        if (g_flag01[row])
            ind = (int)(0xFFFFFFFFu - (uint32_t)(g_best[row] & 0xFFFFFFFFull));
        const float sc = g_scale[ind];
        const float4* px = (const float4*)(x + (size_t)row * DIM);
        const float4* pw = (const float4*)(w + (size_t)ind * DIM);
        float4* po = (float4*)(out0 + (size_t)row * DIM);
        #pragma unroll
        for (int it = 0; it < 4; ++it) {
            int idx = it * 32 + lane;
            float4 wv = pw[idx], xv = px[idx];
            float4 q = make_float4(wv.x * sc, wv.y * sc, wv.z * sc, wv.w * sc);
            po[idx] = q;
            float dx = q.x - xv.x, dy = q.y - xv.y, dz = q.z - xv.z, dw = q.w - xv.w;
            lsum += dx * dx + dy * dy + dz * dz + dw * dw;
        }
        if (write_extra && lane == 0) out_ind[row] = (float)ind;
    }
    #pragma unroll
    for (int o = 16; o; o >>= 1) lsum += __shfl_down_sync(0xffffffffu, lsum, o);
    __shared__ float rs[8];
    if (lane == 0) rs[warp] = lsum;
    __syncthreads();
    if (threadIdx.x == 0) {
        float tt = 0.f;
        #pragma unroll
        for (int i = 0; i < 8; i++) tt += rs[i];
        atomicAdd(&g_diff, tt);
    }
}

__global__ void finalize_kernel(float* __restrict__ diff_out, float inv_cnt) {
    *diff_out = g_diff * inv_cnt;
}

// ---- launch ----
extern "C" void kernel_launch(void* const* d_in, const int* in_sizes, int n_in,
                              void* d_out, int out_size) {
    const float* x = (const float*)d_in[0];
    const float* w = (const float*)d_in[1];
    int xe = in_sizes[0], we = (n_in >= 2) ? in_sizes[1] : 0;
    if (n_in >= 2 && we > xe) { const float* t = x; x = w; w = t; int te = xe; xe = we; we = te; }
    int n = xe / DIM, ne = we / DIM;
    if (n > MAXN) n = MAXN;
    if (ne > MAXNE) ne = MAXNE;
    float* out = (float*)d_out;
    const long long full = (long long)n * DIM + 1 + n;
    const int write_extra = (out_size >= full);

    // fp16 scratch inside d_out (overwritten by gather later)
    __half* xh = (__half*)out;
    __half* wh = (__half*)(out + (size_t)n * DIM / 2);

    cudaFuncSetAttribute(gemm_argmax, cudaFuncAttributeMaxDynamicSharedMemorySize, 196608);

    prep_w<<<ne, 128>>>(w, wh, ne);
    tohalf_kernel<<<(n * DIM / 4 + 255) / 256, 256>>>(x, xh, n * DIM / 4);
    gemm_argmax<<<(n + BM - 1) / BM, 256, 196608>>>(xh, wh, n, ne);
    recheck_kernel<<<148, 256>>>(x, w, ne);
    gather_kernel<<<(n + 7) / 8, 256>>>(x, w, out,
                                        write_extra ? out + (size_t)n * DIM + 1 : out,
                                        write_extra, n);
    if (write_extra)
        finalize_kernel<<<1, 1>>>(out + (size_t)n * DIM, 1.0f / ((float)n * (float)DIM));
}

// round 11
// speedup vs baseline: 3.2708x; 1.4313x over previous
#include <cuda_runtime.h>
#include <cuda_fp16.h>
#include <math.h>
#include <stdint.h>

#define DIM    512
#define MAXN   32768
#define MAXNE  4096
#define MARGIN 4e-3f
#define BM 128

// small scratch only (~680 KB)
__device__ float g_inv_norm[MAXNE];
__device__ float g_scale[MAXNE];
__device__ int   g_ind[MAXN];
__device__ int   g_flag01[MAXN];
__device__ float g_diff;
__device__ int   g_nflag;
__device__ int   g_flag[MAXN];
__device__ unsigned long long g_best[MAXN];

__device__ __forceinline__ uint32_t smem_u32(const void* p) {
    uint32_t a;
    asm("{ .reg .u64 t; cvta.to.shared.u64 t, %1; cvt.u32.u64 %0, t; }" : "=r"(a) : "l"(p));
    return a;
}
__device__ __forceinline__ void cpa16(uint32_t dst, const void* src) {
    asm volatile("cp.async.cg.shared.global [%0], [%1], 16;" :: "r"(dst), "l"(src) : "memory");
}
#define CPC()  asm volatile("cp.async.commit_group;" ::: "memory")
#define CPW(n) asm volatile("cp.async.wait_group %0;" :: "n"(n) : "memory")

__device__ __forceinline__ void ldsm4(uint32_t& a0, uint32_t& a1, uint32_t& a2, uint32_t& a3, uint32_t addr) {
    asm volatile("ldmatrix.sync.aligned.m8n8.x4.shared.b16 {%0,%1,%2,%3}, [%4];"
                 : "=r"(a0), "=r"(a1), "=r"(a2), "=r"(a3) : "r"(addr));
}
__device__ __forceinline__ void mma16816(float* c, const uint32_t* a, const uint32_t* b) {
    asm volatile("mma.sync.aligned.m16n8k16.row.col.f32.f16.f16.f32 "
                 "{%0,%1,%2,%3}, {%4,%5,%6,%7}, {%8,%9}, {%0,%1,%2,%3};"
                 : "+f"(c[0]), "+f"(c[1]), "+f"(c[2]), "+f"(c[3])
                 : "r"(a[0]), "r"(a[1]), "r"(a[2]), "r"(a[3]), "r"(b[0]), "r"(b[1]));
}
__device__ __forceinline__ void upd(float& b, float& s, int& i, float v, int col) {
    if (v > b) { s = b; b = v; i = col; } else if (v > s) s = v;
}
__device__ __forceinline__ void mrg(float& b, float& s, int& i, float ob, float os, int oi) {
    if (ob > b || (ob == b && oi < i)) { s = fmaxf(b, os); b = ob; i = oi; }
    else s = fmaxf(s, ob);
}
__device__ __forceinline__ unsigned long long pack_key(float m, int code) {
    uint32_t u = __float_as_uint(m);
    u = (u & 0x80000000u) ? ~u : (u | 0x80000000u);
    return ((unsigned long long)u << 32) | (0xFFFFFFFFu - (uint32_t)code);
}

// ---- K1: fused norms + w fp16 conversion + resets ----
__global__ void prep_w(const float* __restrict__ w, __half* __restrict__ wh, int ne) {
    int row = blockIdx.x;
    const float* wr = w + (size_t)row * DIM;
    float4 v = ((const float4*)wr)[threadIdx.x];
    float s = v.x*v.x + v.y*v.y + v.z*v.z + v.w*v.w;
    ((__half2*)(wh + (size_t)row * DIM))[threadIdx.x * 2]     = __floats2half2_rn(v.x, v.y);
    ((__half2*)(wh + (size_t)row * DIM))[threadIdx.x * 2 + 1] = __floats2half2_rn(v.z, v.w);
    __shared__ float red[4];
    #pragma unroll
    for (int o = 16; o; o >>= 1) s += __shfl_down_sync(0xffffffffu, s, o);
    if ((threadIdx.x & 31) == 0) red[threadIdx.x >> 5] = s;
    __syncthreads();
    if (threadIdx.x == 0) {
        float t = red[0] + red[1] + red[2] + red[3];
        float nm = sqrtf(t);
        g_inv_norm[row] = 1.0f / nm;
        g_scale[row] = fminf(1.0f, 1.0f / fmaxf(nm, 1e-7f));
        if (row == 0) { g_diff = 0.f; g_nflag = 0; }
    }
}

// ---- K1b: transpose w -> w_t[k][code] (fp32, for recheck) ----
__global__ void transpose_w(const float* __restrict__ w, float* __restrict__ wt, int ne) {
    __shared__ float t[32][33];
    const int c0 = blockIdx.x * 32, k0 = blockIdx.y * 32;
    const int tx = threadIdx.x, ty = threadIdx.y;     // 32 x 8
    #pragma unroll
    for (int i = 0; i < 4; ++i) {
        int code = c0 + ty + i * 8;
        if (code < ne) t[ty + i * 8][tx] = w[(size_t)code * DIM + k0 + tx];
    }
    __syncthreads();
    #pragma unroll
    for (int i = 0; i < 4; ++i) {
        int k = k0 + ty + i * 8;
        int code = c0 + tx;
        if (code < ne) wt[(size_t)k * ne + code] = t[tx][ty + i * 8];
    }
}

// ---- K2: fp32 -> fp16 for x (into d_out scratch) ----
__global__ void tohalf_kernel(const float* __restrict__ src, __half* __restrict__ dst, int n4) {
    int i = blockIdx.x * blockDim.x + threadIdx.x;
    if (i >= n4) return;
    float4 v = ((const float4*)src)[i];
    ((__half2*)dst)[i * 2]     = __floats2half2_rn(v.x, v.y);
    ((__half2*)dst)[i * 2 + 1] = __floats2half2_rn(v.z, v.w);
}

// ---- K3: fp16 HMMA GEMM + fused top-2 argmax, flat chunk pipeline ----
__global__ __launch_bounds__(256, 1)
void gemm_argmax(const __half* __restrict__ xh, const __half* __restrict__ wh,
                 int n, int ne) {
    extern __shared__ char sm[];
    const uint32_t sb = smem_u32(sm);
    const int tid = threadIdx.x, lane = tid & 31, wid = tid >> 5;
    const int wm = wid >> 2, wn = wid & 3;
    const int rowBase = blockIdx.x * BM;
    const int tiles = ne >> 7;
    const int nchunks = tiles * 4;

    auto issue = [&](int h, int st) {
        const int ctb = h >> 2, kb = h & 3;
        #pragma unroll
        for (int i = 0; i < 8; ++i) {
            int idx = tid + i * 256;
            int sub = idx >> 10;
            int rem = idx & 1023;
            int r = rem >> 3, c = rem & 7;
            uint32_t sw = (uint32_t)(sub * 16384 + r * 128 + ((c ^ (r & 7)) << 4));
            int gr = rowBase + r; if (gr >= n) gr = n - 1;
            cpa16(sb + st * 65536 + sw,
                  xh + (size_t)gr * DIM + kb * 128 + sub * 64 + c * 8);
            cpa16(sb + st * 65536 + 32768 + sw,
                  wh + (size_t)(ctb * 128 + r) * DIM + kb * 128 + sub * 64 + c * 8);
        }
        CPC();
    };

    float best[8], second[8];
    int bidx[8];
    #pragma unroll
    for (int s = 0; s < 8; ++s) { best[s] = -3.4e38f; second[s] = -3.4e38f; bidx[s] = 0; }

    float acc[4][4][4];
    #pragma unroll
    for (int mt = 0; mt < 4; ++mt)
        #pragma unroll
        for (int nt = 0; nt < 4; ++nt)
            #pragma unroll
            for (int k = 0; k < 4; ++k) acc[mt][nt][k] = 0.f;

    issue(0, 0);
    issue(1, 1);

    for (int g = 0; g < nchunks; ++g) {
        if (g == nchunks - 1) { CPW(0); } else { CPW(1); }
        __syncthreads();
        if (g + 2 < nchunks) issue(g + 2, (g + 2) % 3);

        const uint32_t ab = sb + (g % 3) * 65536;
        const uint32_t bb = ab + 32768;
        #pragma unroll
        for (int ks = 0; ks < 8; ++ks) {
            const int sub = ks >> 2, ksl = ks & 3;
            const uint32_t abase = ab + sub * 16384;
            const uint32_t bbase = bb + sub * 16384;
            uint32_t a[4][4];
            #pragma unroll
            for (int mt = 0; mt < 4; ++mt) {
                int ar = wm * 64 + mt * 16 + (lane & 15);
                int kc = ksl * 2 + (lane >> 4);
                ldsm4(a[mt][0], a[mt][1], a[mt][2], a[mt][3],
                      abase + ar * 128 + ((kc ^ (ar & 7)) << 4));
            }
            uint32_t bq[2][4];
            #pragma unroll
            for (int p = 0; p < 2; ++p) {
                int br = wn * 32 + p * 16 + (lane & 7) + ((lane >> 4) << 3);
                int kc = ksl * 2 + ((lane >> 3) & 1);
                ldsm4(bq[p][0], bq[p][1], bq[p][2], bq[p][3],
                      bbase + br * 128 + ((kc ^ (br & 7)) << 4));
            }
            #pragma unroll
            for (int mt = 0; mt < 4; ++mt)
                #pragma unroll
                for (int nt = 0; nt < 4; ++nt)
                    mma16816(acc[mt][nt], a[mt], &bq[nt >> 1][(nt & 1) * 2]);
        }

        if ((g & 3) == 3) {
            const int ct = g >> 2;
            #pragma unroll
            for (int nt = 0; nt < 4; ++nt) {
                int col = ct * 128 + wn * 32 + nt * 8 + (lane & 3) * 2;
                float i0 = __ldg(&g_inv_norm[col]);
                float i1 = __ldg(&g_inv_norm[col + 1]);
                #pragma unroll
                for (int mt = 0; mt < 4; ++mt) {
                    int s0 = mt * 2, s1 = mt * 2 + 1;
                    upd(best[s0], second[s0], bidx[s0], acc[mt][nt][0] * i0, col);
                    upd(best[s0], second[s0], bidx[s0], acc[mt][nt][1] * i1, col + 1);
                    upd(best[s1], second[s1], bidx[s1], acc[mt][nt][2] * i0, col);
                    upd(best[s1], second[s1], bidx[s1], acc[mt][nt][3] * i1, col + 1);
                    acc[mt][nt][0] = 0.f; acc[mt][nt][1] = 0.f;
                    acc[mt][nt][2] = 0.f; acc[mt][nt][3] = 0.f;
                }
            }
        }
    }

    #pragma unroll
    for (int s = 0; s < 8; ++s) {
        #pragma unroll
        for (int d = 1; d <= 2; d <<= 1) {
            float ob = __shfl_xor_sync(0xffffffffu, best[s], d);
            float os = __shfl_xor_sync(0xffffffffu, second[s], d);
            int   oi = __shfl_xor_sync(0xffffffffu, bidx[s], d);
            mrg(best[s], second[s], bidx[s], ob, os, oi);
        }
    }

    __syncthreads();
    float* mb = (float*)sm;
    float* ms = mb + 512;
    int*   mi = (int*)(ms + 512);
    if ((lane & 3) == 0) {
        #pragma unroll
        for (int s = 0; s < 8; ++s) {
            int row = wm * 64 + (s >> 1) * 16 + (s & 1) * 8 + (lane >> 2);
            mb[wn * 128 + row] = best[s];
            ms[wn * 128 + row] = second[s];
            mi[wn * 128 + row] = bidx[s];
        }
    }
    __syncthreads();
    if (tid < 128) {
        float bb2 = mb[tid], ss2 = ms[tid];
        int bi = mi[tid];
        #pragma unroll
        for (int w = 1; w < 4; ++w)
            mrg(bb2, ss2, bi, mb[w * 128 + tid], ms[w * 128 + tid], mi[w * 128 + tid]);
        int grow = rowBase + tid;
        if (grow < n) {
            g_ind[grow] = bi;
            int fl = (bb2 - ss2 < MARGIN) ? 1 : 0;
            g_flag01[grow] = fl;
            if (fl) {
                int pos = atomicAdd(&g_nflag, 1);
                if (pos < MAXN) g_flag[pos] = grow;
                g_best[grow] = 0ull;
            }
        }
    }
}

// ---- K4: exact fp32 recheck v2 (lane = code over transposed w) ----
// 256 thr; group = 8 flagged rows; code block = 256 codes, 4 outer iters for ne=1024.
// k-loop accumulates acc[8] per lane: NO shfl, NO atomics in the hot loop.
__global__ __launch_bounds__(256, 1)
void recheck_kernel(const float* __restrict__ x, const float* __restrict__ wt, int ne) {
    __shared__ float xs[8][DIM];
    const int tid = threadIdx.x, lane = tid & 31, warp = tid >> 5;
    int nf = g_nflag; if (nf > MAXN) nf = MAXN;
    for (int base = blockIdx.x * 8; base < nf; base += gridDim.x * 8) {
        int cnt = nf - base; if (cnt > 8) cnt = 8;
        __syncthreads();
        for (int e = tid; e < cnt * DIM; e += 256) {
            int r = e >> 9, k = e & 511;
            xs[r][k] = x[(size_t)g_flag[base + r] * DIM + k];
        }
        __syncthreads();

        unsigned long long bk[8];
        #pragma unroll
        for (int r = 0; r < 8; ++r) bk[r] = 0ull;

        for (int co = 0; co < ne; co += 256) {
            const int code = co + warp * 32 + lane;
            float acc[8];
            #pragma unroll
            for (int r = 0; r < 8; ++r) acc[r] = 0.f;
            for (int kq = 0; kq < DIM / 4; ++kq) {
                const float* wr = wt + (size_t)(kq * 4) * ne + code;
                float w0 = __ldg(wr);
                float w1 = __ldg(wr + ne);
                float w2 = __ldg(wr + 2 * ne);
                float w3 = __ldg(wr + 3 * ne);
                #pragma unroll
                for (int r = 0; r < 8; ++r) {
                    float4 xv = *(const float4*)&xs[r][kq * 4];
                    acc[r] = fmaf(xv.x, w0, fmaf(xv.y, w1, fmaf(xv.z, w2, fmaf(xv.w, w3, acc[r]))));
                }
            }
            float inv = __ldg(&g_inv_norm[code]);
            #pragma unroll
            for (int r = 0; r < 8; ++r) {
                unsigned long long key = pack_key(acc[r] * inv, code);
                if (key > bk[r]) bk[r] = key;
            }
        }

        // warp-reduce the 8 per-lane keys, then one atomic per (warp,row)
        #pragma unroll
        for (int r = 0; r < 8; ++r) {
            #pragma unroll
            for (int o = 16; o; o >>= 1) {
                unsigned long long ok = __shfl_down_sync(0xffffffffu, bk[r], o);
                if (ok > bk[r]) bk[r] = ok;
            }
        }
        if (lane == 0) {
            #pragma unroll
            for (int r = 0; r < 8; ++r)
                if (r < cnt) atomicMax(&g_best[g_flag[base + r]], bk[r]);
        }
    }
}

// ---- K5: gather + MSE (+ inline fix of flagged rows) ----
__global__ void gather_kernel(const float* __restrict__ x, const float* __restrict__ w,
                              float* __restrict__ out0, float* __restrict__ out_ind,
                              int write_extra, int n) {
    const int warp = threadIdx.x >> 5, lane = threadIdx.x & 31;
    const int row = blockIdx.x * 8 + warp;
    float lsum = 0.f;
    if (row < n) {
        int ind = g_ind[row];
        if (g_flag01[row])
            ind = (int)(0xFFFFFFFFu - (uint32_t)(g_best[row] & 0xFFFFFFFFull));
        const float sc = g_scale[ind];
        const float4* px = (const float4*)(x + (size_t)row * DIM);
        const float4* pw = (const float4*)(w + (size_t)ind * DIM);
        float4* po = (float4*)(out0 + (size_t)row * DIM);
        #pragma unroll
        for (int it = 0; it < 4; ++it) {
            int idx = it * 32 + lane;
            float4 wv = pw[idx], xv = px[idx];
            float4 q = make_float4(wv.x * sc, wv.y * sc, wv.z * sc, wv.w * sc);
            po[idx] = q;
            float dx = q.x - xv.x, dy = q.y - xv.y, dz = q.z - xv.z, dw = q.w - xv.w;
            lsum += dx * dx + dy * dy + dz * dz + dw * dw;
        }
        if (write_extra && lane == 0) out_ind[row] = (float)ind;
    }
    #pragma unroll
    for (int o = 16; o; o >>= 1) lsum += __shfl_down_sync(0xffffffffu, lsum, o);
    __shared__ float rs[8];
    if (lane == 0) rs[warp] = lsum;
    __syncthreads();
    if (threadIdx.x == 0) {
        float tt = 0.f;
        #pragma unroll
        for (int i = 0; i < 8; i++) tt += rs[i];
        atomicAdd(&g_diff, tt);
    }
}

__global__ void finalize_kernel(float* __restrict__ diff_out, float inv_cnt) {
    *diff_out = g_diff * inv_cnt;
}

// ---- launch ----
extern "C" void kernel_launch(void* const* d_in, const int* in_sizes, int n_in,
                              void* d_out, int out_size) {
    const float* x = (const float*)d_in[0];
    const float* w = (const float*)d_in[1];
    int xe = in_sizes[0], we = (n_in >= 2) ? in_sizes[1] : 0;
    if (n_in >= 2 && we > xe) { const float* t = x; x = w; w = t; int te = xe; xe = we; we = te; }
    int n = xe / DIM, ne = we / DIM;
    if (n > MAXN) n = MAXN;
    if (ne > MAXNE) ne = MAXNE;
    float* out = (float*)d_out;
    const long long full = (long long)n * DIM + 1 + n;
    const int write_extra = (out_size >= full);

    // scratch inside d_out (all overwritten by gather later):
    __half* xh = (__half*)out;                                  // n*DIM halves
    __half* wh = (__half*)(out + (size_t)n * DIM / 2);          // ne*DIM halves
    float*  wt = out + (size_t)n * DIM / 2 + (size_t)ne * DIM / 2;  // ne*DIM floats

    cudaFuncSetAttribute(gemm_argmax, cudaFuncAttributeMaxDynamicSharedMemorySize, 196608);

    prep_w<<<ne, 128>>>(w, wh, ne);
    transpose_w<<<dim3((ne + 31) / 32, (DIM + 31) / 32), dim3(32, 8)>>>(w, wt, ne);
    tohalf_kernel<<<(n * DIM / 4 + 255) / 256, 256>>>(x, xh, n * DIM / 4);
    gemm_argmax<<<(n + BM - 1) / BM, 256, 196608>>>(xh, wh, n, ne);
    recheck_kernel<<<256, 256>>>(x, wt, ne);
    gather_kernel<<<(n + 7) / 8, 256>>>(x, w, out,
                                        write_extra ? out + (size_t)n * DIM + 1 : out,
                                        write_extra, n);
    if (write_extra)
        finalize_kernel<<<1, 1>>>(out + (size_t)n * DIM, 1.0f / ((float)n * (float)DIM));
}

// round 12
// speedup vs baseline: 3.2937x; 1.0070x over previous
#include <cuda_runtime.h>
#include <cuda_fp16.h>
#include <math.h>
#include <stdint.h>

#define DIM    512
#define MAXN   32768
#define MAXNE  4096
#define MARGIN 4e-3f
#define BM 128

__device__ float g_inv_norm[MAXNE];
__device__ float g_scale[MAXNE];
__device__ int   g_ind[MAXN];
__device__ int   g_flag01[MAXN];
__device__ float g_diff;
__device__ int   g_nflag;
__device__ int   g_done;
__device__ int   g_flag[MAXN];
__device__ unsigned long long g_best[MAXN];

__device__ __forceinline__ uint32_t smem_u32(const void* p) {
    uint32_t a;
    asm("{ .reg .u64 t; cvta.to.shared.u64 t, %1; cvt.u32.u64 %0, t; }" : "=r"(a) : "l"(p));
    return a;
}
__device__ __forceinline__ void cpa16(uint32_t dst, const void* src) {
    asm volatile("cp.async.cg.shared.global [%0], [%1], 16;" :: "r"(dst), "l"(src) : "memory");
}
#define CPC()  asm volatile("cp.async.commit_group;" ::: "memory")
#define CPW(n) asm volatile("cp.async.wait_group %0;" :: "n"(n) : "memory")

__device__ __forceinline__ void ldsm4(uint32_t& a0, uint32_t& a1, uint32_t& a2, uint32_t& a3, uint32_t addr) {
    asm volatile("ldmatrix.sync.aligned.m8n8.x4.shared.b16 {%0,%1,%2,%3}, [%4];"
                 : "=r"(a0), "=r"(a1), "=r"(a2), "=r"(a3) : "r"(addr));
}
__device__ __forceinline__ void mma16816(float* c, const uint32_t* a, const uint32_t* b) {
    asm volatile("mma.sync.aligned.m16n8k16.row.col.f32.f16.f16.f32 "
                 "{%0,%1,%2,%3}, {%4,%5,%6,%7}, {%8,%9}, {%0,%1,%2,%3};"
                 : "+f"(c[0]), "+f"(c[1]), "+f"(c[2]), "+f"(c[3])
                 : "r"(a[0]), "r"(a[1]), "r"(a[2]), "r"(a[3]), "r"(b[0]), "r"(b[1]));
}
__device__ __forceinline__ void upd(float& b, float& s, int& i, float v, int col) {
    if (v > b) { s = b; b = v; i = col; } else if (v > s) s = v;
}
__device__ __forceinline__ void mrg(float& b, float& s, int& i, float ob, float os, int oi) {
    if (ob > b || (ob == b && oi < i)) { s = fmaxf(b, os); b = ob; i = oi; }
    else s = fmaxf(s, ob);
}
__device__ __forceinline__ unsigned long long pack_key(float m, int code) {
    uint32_t u = __float_as_uint(m);
    u = (u & 0x80000000u) ? ~u : (u | 0x80000000u);
    return ((unsigned long long)u << 32) | (0xFFFFFFFFu - (uint32_t)code);
}

// ---- K1: fused norms + w fp16 + w transpose + resets ----
__global__ void prep_w(const float* __restrict__ w, __half* __restrict__ wh,
                       float* __restrict__ wt, int ne) {
    int row = blockIdx.x;
    const float* wr = w + (size_t)row * DIM;
    float4 v = ((const float4*)wr)[threadIdx.x];
    float s = v.x*v.x + v.y*v.y + v.z*v.z + v.w*v.w;
    ((__half2*)(wh + (size_t)row * DIM))[threadIdx.x * 2]     = __floats2half2_rn(v.x, v.y);
    ((__half2*)(wh + (size_t)row * DIM))[threadIdx.x * 2 + 1] = __floats2half2_rn(v.z, v.w);
    int k = threadIdx.x * 4;
    wt[(size_t)k * ne + row] = v.x;
    wt[(size_t)(k + 1) * ne + row] = v.y;
    wt[(size_t)(k + 2) * ne + row] = v.z;
    wt[(size_t)(k + 3) * ne + row] = v.w;
    __shared__ float red[4];
    #pragma unroll
    for (int o = 16; o; o >>= 1) s += __shfl_down_sync(0xffffffffu, s, o);
    if ((threadIdx.x & 31) == 0) red[threadIdx.x >> 5] = s;
    __syncthreads();
    if (threadIdx.x == 0) {
        float t = red[0] + red[1] + red[2] + red[3];
        float nm = sqrtf(t);
        g_inv_norm[row] = 1.0f / nm;
        g_scale[row] = fminf(1.0f, 1.0f / fmaxf(nm, 1e-7f));
        if (row == 0) { g_diff = 0.f; g_nflag = 0; g_done = 0; }
    }
}

// ---- K2: fp32 -> fp16 for x ----
__global__ void tohalf_kernel(const float* __restrict__ src, __half* __restrict__ dst, int n4) {
    int i = blockIdx.x * blockDim.x + threadIdx.x;
    if (i >= n4) return;
    float4 v = ((const float4*)src)[i];
    ((__half2*)dst)[i * 2]     = __floats2half2_rn(v.x, v.y);
    ((__half2*)dst)[i * 2 + 1] = __floats2half2_rn(v.z, v.w);
}

// ---- K3: HMMA GEMM + top-2 argmax; A persistent in smem, B-only pipeline ----
// smem: A 128KB (4 kb-blocks of 32KB) + B 3 stages x 32KB = 224KB.
// 256 thr = 8 warps (2M x 4N), CTA tile 128x128, warp tile 64x32.
__global__ __launch_bounds__(256, 1)
void gemm_argmax(const __half* __restrict__ xh, const __half* __restrict__ wh,
                 int n, int ne) {
    extern __shared__ char sm[];
    const uint32_t sb = smem_u32(sm);
    const uint32_t sbB = sb + 131072;
    const int tid = threadIdx.x, lane = tid & 31, wid = tid >> 5;
    const int wm = wid >> 2, wn = wid & 3;
    const int rowBase = blockIdx.x * BM;
    const int tiles = ne >> 7;
    const int nchunks = tiles * 4;

    auto issueB = [&](int h, int st) {
        const int ctb = h >> 2, kb = h & 3;
        #pragma unroll
        for (int i = 0; i < 8; ++i) {
            int idx = tid + i * 256;         // 0..2047
            int sub = idx >> 10, rem = idx & 1023;
            int r = rem >> 3, c = rem & 7;
            uint32_t sw = (uint32_t)(sub * 16384 + r * 128 + ((c ^ (r & 7)) << 4));
            cpa16(sbB + st * 32768 + sw,
                  wh + (size_t)(ctb * 128 + r) * DIM + kb * 128 + sub * 64 + c * 8);
        }
        CPC();
    };

    // load A once: 4 kb-blocks, 32 cp.async per thread; same group as B0
    #pragma unroll
    for (int kb = 0; kb < 4; ++kb) {
        #pragma unroll
        for (int i = 0; i < 8; ++i) {
            int idx = tid + i * 256;
            int sub = idx >> 10, rem = idx & 1023;
            int r = rem >> 3, c = rem & 7;
            uint32_t sw = (uint32_t)(sub * 16384 + r * 128 + ((c ^ (r & 7)) << 4));
            int gr = rowBase + r; if (gr >= n) gr = n - 1;
            cpa16(sb + kb * 32768 + sw,
                  xh + (size_t)gr * DIM + kb * 128 + sub * 64 + c * 8);
        }
    }
    {
        const int h = 0, st = 0, ctb = 0, kb = 0;
        #pragma unroll
        for (int i = 0; i < 8; ++i) {
            int idx = tid + i * 256;
            int sub = idx >> 10, rem = idx & 1023;
            int r = rem >> 3, c = rem & 7;
            uint32_t sw = (uint32_t)(sub * 16384 + r * 128 + ((c ^ (r & 7)) << 4));
            cpa16(sbB + st * 32768 + sw,
                  wh + (size_t)(ctb * 128 + r) * DIM + kb * 128 + sub * 64 + c * 8);
        }
        CPC();
        (void)h;
    }
    issueB(1, 1);

    float best[8], second[8];
    int bidx[8];
    #pragma unroll
    for (int s = 0; s < 8; ++s) { best[s] = -3.4e38f; second[s] = -3.4e38f; bidx[s] = 0; }

    float acc[4][4][4];
    #pragma unroll
    for (int mt = 0; mt < 4; ++mt)
        #pragma unroll
        for (int nt = 0; nt < 4; ++nt)
            #pragma unroll
            for (int k = 0; k < 4; ++k) acc[mt][nt][k] = 0.f;

    for (int g = 0; g < nchunks; ++g) {
        if (g == nchunks - 1) { CPW(0); } else { CPW(1); }
        __syncthreads();
        if (g + 2 < nchunks) issueB(g + 2, (g + 2) % 3);

        const uint32_t ablk = sb + (g & 3) * 32768;
        const uint32_t bblk = sbB + (g % 3) * 32768;
        #pragma unroll
        for (int ks = 0; ks < 8; ++ks) {
            const int sub = ks >> 2, ksl = ks & 3;
            const uint32_t abase = ablk + sub * 16384;
            const uint32_t bbase = bblk + sub * 16384;
            uint32_t a[4][4];
            #pragma unroll
            for (int mt = 0; mt < 4; ++mt) {
                int ar = wm * 64 + mt * 16 + (lane & 15);
                int kc = ksl * 2 + (lane >> 4);
                ldsm4(a[mt][0], a[mt][1], a[mt][2], a[mt][3],
                      abase + ar * 128 + ((kc ^ (ar & 7)) << 4));
            }
            uint32_t bq[2][4];
            #pragma unroll
            for (int p = 0; p < 2; ++p) {
                int br = wn * 32 + p * 16 + (lane & 7) + ((lane >> 4) << 3);
                int kc = ksl * 2 + ((lane >> 3) & 1);
                ldsm4(bq[p][0], bq[p][1], bq[p][2], bq[p][3],
                      bbase + br * 128 + ((kc ^ (br & 7)) << 4));
            }
            #pragma unroll
            for (int mt = 0; mt < 4; ++mt)
                #pragma unroll
                for (int nt = 0; nt < 4; ++nt)
                    mma16816(acc[mt][nt], a[mt], &bq[nt >> 1][(nt & 1) * 2]);
        }

        if ((g & 3) == 3) {
            const int ct = g >> 2;
            #pragma unroll
            for (int nt = 0; nt < 4; ++nt) {
                int col = ct * 128 + wn * 32 + nt * 8 + (lane & 3) * 2;
                float i0 = __ldg(&g_inv_norm[col]);
                float i1 = __ldg(&g_inv_norm[col + 1]);
                #pragma unroll
                for (int mt = 0; mt < 4; ++mt) {
                    int s0 = mt * 2, s1 = mt * 2 + 1;
                    upd(best[s0], second[s0], bidx[s0], acc[mt][nt][0] * i0, col);
                    upd(best[s0], second[s0], bidx[s0], acc[mt][nt][1] * i1, col + 1);
                    upd(best[s1], second[s1], bidx[s1], acc[mt][nt][2] * i0, col);
                    upd(best[s1], second[s1], bidx[s1], acc[mt][nt][3] * i1, col + 1);
                    acc[mt][nt][0] = 0.f; acc[mt][nt][1] = 0.f;
                    acc[mt][nt][2] = 0.f; acc[mt][nt][3] = 0.f;
                }
            }
        }
    }

    #pragma unroll
    for (int s = 0; s < 8; ++s) {
        #pragma unroll
        for (int d = 1; d <= 2; d <<= 1) {
            float ob = __shfl_xor_sync(0xffffffffu, best[s], d);
            float os = __shfl_xor_sync(0xffffffffu, second[s], d);
            int   oi = __shfl_xor_sync(0xffffffffu, bidx[s], d);
            mrg(best[s], second[s], bidx[s], ob, os, oi);
        }
    }

    __syncthreads();
    float* mb = (float*)sm;
    float* ms = mb + 512;
    int*   mi = (int*)(ms + 512);
    if ((lane & 3) == 0) {
        #pragma unroll
        for (int s = 0; s < 8; ++s) {
            int row = wm * 64 + (s >> 1) * 16 + (s & 1) * 8 + (lane >> 2);
            mb[wn * 128 + row] = best[s];
            ms[wn * 128 + row] = second[s];
            mi[wn * 128 + row] = bidx[s];
        }
    }
    __syncthreads();
    if (tid < 128) {
        float bb2 = mb[tid], ss2 = ms[tid];
        int bi = mi[tid];
        #pragma unroll
        for (int w = 1; w < 4; ++w)
            mrg(bb2, ss2, bi, mb[w * 128 + tid], ms[w * 128 + tid], mi[w * 128 + tid]);
        int grow = rowBase + tid;
        if (grow < n) {
            g_ind[grow] = bi;
            int fl = (bb2 - ss2 < MARGIN) ? 1 : 0;
            g_flag01[grow] = fl;
            if (fl) {
                int pos = atomicAdd(&g_nflag, 1);
                if (pos < MAXN) g_flag[pos] = grow;
                g_best[grow] = 0ull;
            }
        }
    }
}

// ---- K4: exact fp32 recheck (lane = code over transposed w) ----
__global__ __launch_bounds__(256, 1)
void recheck_kernel(const float* __restrict__ x, const float* __restrict__ wt, int ne) {
    __shared__ float xs[8][DIM];
    const int tid = threadIdx.x, lane = tid & 31, warp = tid >> 5;
    int nf = g_nflag; if (nf > MAXN) nf = MAXN;
    for (int base = blockIdx.x * 8; base < nf; base += gridDim.x * 8) {
        int cnt = nf - base; if (cnt > 8) cnt = 8;
        __syncthreads();
        for (int e = tid; e < cnt * DIM; e += 256) {
            int r = e >> 9, k = e & 511;
            xs[r][k] = x[(size_t)g_flag[base + r] * DIM + k];
        }
        __syncthreads();

        unsigned long long bk[8];
        #pragma unroll
        for (int r = 0; r < 8; ++r) bk[r] = 0ull;

        for (int co = 0; co < ne; co += 256) {
            const int code = co + warp * 32 + lane;
            float acc[8];
            #pragma unroll
            for (int r = 0; r < 8; ++r) acc[r] = 0.f;
            for (int kq = 0; kq < DIM / 4; ++kq) {
                const float* wr = wt + (size_t)(kq * 4) * ne + code;
                float w0 = __ldg(wr);
                float w1 = __ldg(wr + ne);
                float w2 = __ldg(wr + 2 * ne);
                float w3 = __ldg(wr + 3 * ne);
                #pragma unroll
                for (int r = 0; r < 8; ++r) {
                    float4 xv = *(const float4*)&xs[r][kq * 4];
                    acc[r] = fmaf(xv.x, w0, fmaf(xv.y, w1, fmaf(xv.z, w2, fmaf(xv.w, w3, acc[r]))));
                }
            }
            float inv = __ldg(&g_inv_norm[code]);
            #pragma unroll
            for (int r = 0; r < 8; ++r) {
                unsigned long long key = pack_key(acc[r] * inv, code);
                if (key > bk[r]) bk[r] = key;
            }
        }
        #pragma unroll
        for (int r = 0; r < 8; ++r) {
            #pragma unroll
            for (int o = 16; o; o >>= 1) {
                unsigned long long ok = __shfl_down_sync(0xffffffffu, bk[r], o);
                if (ok > bk[r]) bk[r] = ok;
            }
        }
        if (lane == 0) {
            #pragma unroll
            for (int r = 0; r < 8; ++r)
                if (r < cnt) atomicMax(&g_best[g_flag[base + r]], bk[r]);
        }
    }
}

// ---- K5: gather + MSE + fused finalize (last-block pattern) ----
__global__ void gather_kernel(const float* __restrict__ x, const float* __restrict__ w,
                              float* __restrict__ out0, float* __restrict__ out_ind,
                              float* __restrict__ diff_out, float inv_cnt,
                              int write_extra, int n) {
    const int warp = threadIdx.x >> 5, lane = threadIdx.x & 31;
    const int row = blockIdx.x * 8 + warp;
    float lsum = 0.f;
    if (row < n) {
        int ind = g_ind[row];
        if (g_flag01[row])
            ind = (int)(0xFFFFFFFFu - (uint32_t)(g_best[row] & 0xFFFFFFFFull));
        const float sc = g_scale[ind];
        const float4* px = (const float4*)(x + (size_t)row * DIM);
        const float4* pw = (const float4*)(w + (size_t)ind * DIM);
        float4* po = (float4*)(out0 + (size_t)row * DIM);
        #pragma unroll
        for (int it = 0; it < 4; ++it) {
            int idx = it * 32 + lane;
            float4 wv = pw[idx], xv = px[idx];
            float4 q = make_float4(wv.x * sc, wv.y * sc, wv.z * sc, wv.w * sc);
            po[idx] = q;
            float dx = q.x - xv.x, dy = q.y - xv.y, dz = q.z - xv.z, dw = q.w - xv.w;
            lsum += dx * dx + dy * dy + dz * dz + dw * dw;
        }
        if (write_extra && lane == 0) out_ind[row] = (float)ind;
    }
    #pragma unroll
    for (int o = 16; o; o >>= 1) lsum += __shfl_down_sync(0xffffffffu, lsum, o);
    __shared__ float rs[8];
    if (lane == 0) rs[warp] = lsum;
    __syncthreads();
    if (threadIdx.x == 0) {
        float tt = 0.f;
        #pragma unroll
        for (int i = 0; i < 8; i++) tt += rs[i];
        atomicAdd(&g_diff, tt);
        __threadfence();
        int done = atomicAdd(&g_done, 1);
        if (write_extra && done == gridDim.x - 1)
            *diff_out = g_diff * inv_cnt;
    }
}

// ---- launch ----
extern "C" void kernel_launch(void* const* d_in, const int* in_sizes, int n_in,
                              void* d_out, int out_size) {
    const float* x = (const float*)d_in[0];
    const float* w = (const float*)d_in[1];
    int xe = in_sizes[0], we = (n_in >= 2) ? in_sizes[1] : 0;
    if (n_in >= 2 && we > xe) { const float* t = x; x = w; w = t; int te = xe; xe = we; we = te; }
    int n = xe / DIM, ne = we / DIM;
    if (n > MAXN) n = MAXN;
    if (ne > MAXNE) ne = MAXNE;
    float* out = (float*)d_out;
    const long long full = (long long)n * DIM + 1 + n;
    const int write_extra = (out_size >= full);

    // scratch inside d_out (all overwritten by gather later):
    __half* xh = (__half*)out;
    __half* wh = (__half*)(out + (size_t)n * DIM / 2);
    float*  wt = out + (size_t)n * DIM / 2 + (size_t)ne * DIM / 2;

    cudaFuncSetAttribute(gemm_argmax, cudaFuncAttributeMaxDynamicSharedMemorySize, 229376);

    prep_w<<<ne, 128>>>(w, wh, wt, ne);
    tohalf_kernel<<<(n * DIM / 4 + 255) / 256, 256>>>(x, xh, n * DIM / 4);
    gemm_argmax<<<(n + BM - 1) / BM, 256, 229376>>>(xh, wh, n, ne);
    recheck_kernel<<<256, 256>>>(x, wt, ne);
    gather_kernel<<<(n + 7) / 8, 256>>>(x, w, out,
                                        write_extra ? out + (size_t)n * DIM + 1 : out,
                                        out + (size_t)n * DIM,
                                        1.0f / ((float)n * (float)DIM),
                                        write_extra, n);
}

// round 13
// speedup vs baseline: 4.2635x; 1.2944x over previous
#include <cuda_runtime.h>
#include <cuda_fp16.h>
#include <math.h>
#include <stdint.h>

#define DIM    512
#define MAXN   32768
#define MAXNE  4096
#define MARGIN 4e-3f
#define BM 128

__device__ float g_inv_norm[MAXNE];
__device__ float g_scale[MAXNE];
__device__ int   g_ind[MAXN];
__device__ int   g_flag01[MAXN];
__device__ float g_diff;
__device__ int   g_nflag;
__device__ int   g_done;
__device__ int   g_flag[MAXN];
__device__ unsigned long long g_best[MAXN];

__device__ __forceinline__ uint32_t smem_u32(const void* p) {
    uint32_t a;
    asm("{ .reg .u64 t; cvta.to.shared.u64 t, %1; cvt.u32.u64 %0, t; }" : "=r"(a) : "l"(p));
    return a;
}
__device__ __forceinline__ void cpa16(uint32_t dst, const void* src) {
    asm volatile("cp.async.cg.shared.global [%0], [%1], 16;" :: "r"(dst), "l"(src) : "memory");
}
#define CPC()  asm volatile("cp.async.commit_group;" ::: "memory")
#define CPW(n) asm volatile("cp.async.wait_group %0;" :: "n"(n) : "memory")

__device__ __forceinline__ void ldsm4(uint32_t& a0, uint32_t& a1, uint32_t& a2, uint32_t& a3, uint32_t addr) {
    asm volatile("ldmatrix.sync.aligned.m8n8.x4.shared.b16 {%0,%1,%2,%3}, [%4];"
                 : "=r"(a0), "=r"(a1), "=r"(a2), "=r"(a3) : "r"(addr));
}
__device__ __forceinline__ void mma16816(float* c, const uint32_t* a, const uint32_t* b) {
    asm volatile("mma.sync.aligned.m16n8k16.row.col.f32.f16.f16.f32 "
                 "{%0,%1,%2,%3}, {%4,%5,%6,%7}, {%8,%9}, {%0,%1,%2,%3};"
                 : "+f"(c[0]), "+f"(c[1]), "+f"(c[2]), "+f"(c[3])
                 : "r"(a[0]), "r"(a[1]), "r"(a[2]), "r"(a[3]), "r"(b[0]), "r"(b[1]));
}
__device__ __forceinline__ void upd(float& b, float& s, int& i, float v, int col) {
    if (v > b) { s = b; b = v; i = col; } else if (v > s) s = v;
}
__device__ __forceinline__ void mrg(float& b, float& s, int& i, float ob, float os, int oi) {
    if (ob > b || (ob == b && oi < i)) { s = fmaxf(b, os); b = ob; i = oi; }
    else s = fmaxf(s, ob);
}
__device__ __forceinline__ unsigned long long pack_key(float m, int code) {
    uint32_t u = __float_as_uint(m);
    u = (u & 0x80000000u) ? ~u : (u | 0x80000000u);
    return ((unsigned long long)u << 32) | (0xFFFFFFFFu - (uint32_t)code);
}

// ---- K1: fused norms + w fp16 + w transpose + resets ----
__global__ void prep_w(const float* __restrict__ w, __half* __restrict__ wh,
                       float* __restrict__ wt, int ne) {
    int row = blockIdx.x;
    const float* wr = w + (size_t)row * DIM;
    float4 v = ((const float4*)wr)[threadIdx.x];
    float s = v.x*v.x + v.y*v.y + v.z*v.z + v.w*v.w;
    ((__half2*)(wh + (size_t)row * DIM))[threadIdx.x * 2]     = __floats2half2_rn(v.x, v.y);
    ((__half2*)(wh + (size_t)row * DIM))[threadIdx.x * 2 + 1] = __floats2half2_rn(v.z, v.w);
    int k = threadIdx.x * 4;
    wt[(size_t)k * ne + row] = v.x;
    wt[(size_t)(k + 1) * ne + row] = v.y;
    wt[(size_t)(k + 2) * ne + row] = v.z;
    wt[(size_t)(k + 3) * ne + row] = v.w;
    __shared__ float red[4];
    #pragma unroll
    for (int o = 16; o; o >>= 1) s += __shfl_down_sync(0xffffffffu, s, o);
    if ((threadIdx.x & 31) == 0) red[threadIdx.x >> 5] = s;
    __syncthreads();
    if (threadIdx.x == 0) {
        float t = red[0] + red[1] + red[2] + red[3];
        float nm = sqrtf(t);
        g_inv_norm[row] = 1.0f / nm;
        g_scale[row] = fminf(1.0f, 1.0f / fmaxf(nm, 1e-7f));
        if (row == 0) { g_diff = 0.f; g_nflag = 0; g_done = 0; }
    }
}

// ---- K2: fp32 -> fp16 for x ----
__global__ void tohalf_kernel(const float* __restrict__ src, __half* __restrict__ dst, int n4) {
    int i = blockIdx.x * blockDim.x + threadIdx.x;
    if (i >= n4) return;
    float4 v = ((const float4*)src)[i];
    ((__half2*)dst)[i * 2]     = __floats2half2_rn(v.x, v.y);
    ((__half2*)dst)[i * 2 + 1] = __floats2half2_rn(v.z, v.w);
}

// ---- K3: HMMA GEMM + top-2 argmax; A persistent in smem, B-only pipeline ----
__global__ __launch_bounds__(256, 1)
void gemm_argmax(const __half* __restrict__ xh, const __half* __restrict__ wh,
                 int n, int ne) {
    extern __shared__ char sm[];
    const uint32_t sb = smem_u32(sm);
    const uint32_t sbB = sb + 131072;
    const int tid = threadIdx.x, lane = tid & 31, wid = tid >> 5;
    const int wm = wid >> 2, wn = wid & 3;
    const int rowBase = blockIdx.x * BM;
    const int tiles = ne >> 7;
    const int nchunks = tiles * 4;

    auto issueB = [&](int h, int st) {
        const int ctb = h >> 2, kb = h & 3;
        #pragma unroll
        for (int i = 0; i < 8; ++i) {
            int idx = tid + i * 256;
            int sub = idx >> 10, rem = idx & 1023;
            int r = rem >> 3, c = rem & 7;
            uint32_t sw = (uint32_t)(sub * 16384 + r * 128 + ((c ^ (r & 7)) << 4));
            cpa16(sbB + st * 32768 + sw,
                  wh + (size_t)(ctb * 128 + r) * DIM + kb * 128 + sub * 64 + c * 8);
        }
        CPC();
    };

    #pragma unroll
    for (int kb = 0; kb < 4; ++kb) {
        #pragma unroll
        for (int i = 0; i < 8; ++i) {
            int idx = tid + i * 256;
            int sub = idx >> 10, rem = idx & 1023;
            int r = rem >> 3, c = rem & 7;
            uint32_t sw = (uint32_t)(sub * 16384 + r * 128 + ((c ^ (r & 7)) << 4));
            int gr = rowBase + r; if (gr >= n) gr = n - 1;
            cpa16(sb + kb * 32768 + sw,
                  xh + (size_t)gr * DIM + kb * 128 + sub * 64 + c * 8);
        }
    }
    {
        #pragma unroll
        for (int i = 0; i < 8; ++i) {
            int idx = tid + i * 256;
            int sub = idx >> 10, rem = idx & 1023;
            int r = rem >> 3, c = rem & 7;
            uint32_t sw = (uint32_t)(sub * 16384 + r * 128 + ((c ^ (r & 7)) << 4));
            cpa16(sbB + sw, wh + (size_t)r * DIM + sub * 64 + c * 8);
        }
        CPC();
    }
    issueB(1, 1);

    float best[8], second[8];
    int bidx[8];
    #pragma unroll
    for (int s = 0; s < 8; ++s) { best[s] = -3.4e38f; second[s] = -3.4e38f; bidx[s] = 0; }

    float acc[4][4][4];
    #pragma unroll
    for (int mt = 0; mt < 4; ++mt)
        #pragma unroll
        for (int nt = 0; nt < 4; ++nt)
            #pragma unroll
            for (int k = 0; k < 4; ++k) acc[mt][nt][k] = 0.f;

    for (int g = 0; g < nchunks; ++g) {
        if (g == nchunks - 1) { CPW(0); } else { CPW(1); }
        __syncthreads();
        if (g + 2 < nchunks) issueB(g + 2, (g + 2) % 3);

        const uint32_t ablk = sb + (g & 3) * 32768;
        const uint32_t bblk = sbB + (g % 3) * 32768;
        #pragma unroll
        for (int ks = 0; ks < 8; ++ks) {
            const int sub = ks >> 2, ksl = ks & 3;
            const uint32_t abase = ablk + sub * 16384;
            const uint32_t bbase = bblk + sub * 16384;
            uint32_t a[4][4];
            #pragma unroll
            for (int mt = 0; mt < 4; ++mt) {
                int ar = wm * 64 + mt * 16 + (lane & 15);
                int kc = ksl * 2 + (lane >> 4);
                ldsm4(a[mt][0], a[mt][1], a[mt][2], a[mt][3],
                      abase + ar * 128 + ((kc ^ (ar & 7)) << 4));
            }
            uint32_t bq[2][4];
            #pragma unroll
            for (int p = 0; p < 2; ++p) {
                int br = wn * 32 + p * 16 + (lane & 7) + ((lane >> 4) << 3);
                int kc = ksl * 2 + ((lane >> 3) & 1);
                ldsm4(bq[p][0], bq[p][1], bq[p][2], bq[p][3],
                      bbase + br * 128 + ((kc ^ (br & 7)) << 4));
            }
            #pragma unroll
            for (int mt = 0; mt < 4; ++mt)
                #pragma unroll
                for (int nt = 0; nt < 4; ++nt)
                    mma16816(acc[mt][nt], a[mt], &bq[nt >> 1][(nt & 1) * 2]);
        }

        if ((g & 3) == 3) {
            const int ct = g >> 2;
            #pragma unroll
            for (int nt = 0; nt < 4; ++nt) {
                int col = ct * 128 + wn * 32 + nt * 8 + (lane & 3) * 2;
                float i0 = __ldg(&g_inv_norm[col]);
                float i1 = __ldg(&g_inv_norm[col + 1]);
                #pragma unroll
                for (int mt = 0; mt < 4; ++mt) {
                    int s0 = mt * 2, s1 = mt * 2 + 1;
                    upd(best[s0], second[s0], bidx[s0], acc[mt][nt][0] * i0, col);
                    upd(best[s0], second[s0], bidx[s0], acc[mt][nt][1] * i1, col + 1);
                    upd(best[s1], second[s1], bidx[s1], acc[mt][nt][2] * i0, col);
                    upd(best[s1], second[s1], bidx[s1], acc[mt][nt][3] * i1, col + 1);
                    acc[mt][nt][0] = 0.f; acc[mt][nt][1] = 0.f;
                    acc[mt][nt][2] = 0.f; acc[mt][nt][3] = 0.f;
                }
            }
        }
    }

    #pragma unroll
    for (int s = 0; s < 8; ++s) {
        #pragma unroll
        for (int d = 1; d <= 2; d <<= 1) {
            float ob = __shfl_xor_sync(0xffffffffu, best[s], d);
            float os = __shfl_xor_sync(0xffffffffu, second[s], d);
            int   oi = __shfl_xor_sync(0xffffffffu, bidx[s], d);
            mrg(best[s], second[s], bidx[s], ob, os, oi);
        }
    }

    __syncthreads();
    float* mb = (float*)sm;
    float* ms = mb + 512;
    int*   mi = (int*)(ms + 512);
    if ((lane & 3) == 0) {
        #pragma unroll
        for (int s = 0; s < 8; ++s) {
            int row = wm * 64 + (s >> 1) * 16 + (s & 1) * 8 + (lane >> 2);
            mb[wn * 128 + row] = best[s];
            ms[wn * 128 + row] = second[s];
            mi[wn * 128 + row] = bidx[s];
        }
    }
    __syncthreads();
    if (tid < 128) {
        float bb2 = mb[tid], ss2 = ms[tid];
        int bi = mi[tid];
        #pragma unroll
        for (int w = 1; w < 4; ++w)
            mrg(bb2, ss2, bi, mb[w * 128 + tid], ms[w * 128 + tid], mi[w * 128 + tid]);
        int grow = rowBase + tid;
        if (grow < n) {
            g_ind[grow] = bi;
            int fl = (bb2 - ss2 < MARGIN) ? 1 : 0;
            g_flag01[grow] = fl;
            if (fl) {
                int pos = atomicAdd(&g_nflag, 1);
                if (pos < MAXN) g_flag[pos] = grow;
                g_best[grow] = 0ull;
            }
        }
    }
}

// ---- K4: exact fp32 recheck v3: (8-row group) x (256-code slice) items ----
// 256 thr = 256 codes per slice; k-loop unrolled x4 -> 16 loads in flight.
__global__ __launch_bounds__(256, 1)
void recheck_kernel(const float* __restrict__ x, const float* __restrict__ wt, int ne) {
    __shared__ float xs[8][DIM];
    const int tid = threadIdx.x, lane = tid & 31, warp = tid >> 5;
    int nf = g_nflag; if (nf > MAXN) nf = MAXN;
    const int ngroups = (nf + 7) >> 3;
    const int nslice = ne >> 8;            // 256-code slices (ne multiple of 256)
    const int total = ngroups * nslice;

    for (int wk = blockIdx.x; wk < total; wk += gridDim.x) {
        const int grp = wk / nslice, slice = wk - grp * nslice;
        const int base = grp * 8;
        int cnt = nf - base; if (cnt > 8) cnt = 8;
        __syncthreads();
        for (int e = tid; e < cnt * DIM; e += 256) {
            int r = e >> 9, k = e & 511;
            xs[r][k] = x[(size_t)g_flag[base + r] * DIM + k];
        }
        __syncthreads();

        const int code = slice * 256 + tid;
        float acc[8];
        #pragma unroll
        for (int r = 0; r < 8; ++r) acc[r] = 0.f;

        for (int kq0 = 0; kq0 < DIM / 4; kq0 += 4) {
            float wv[16];
            #pragma unroll
            for (int u = 0; u < 4; ++u) {
                const float* wr = wt + (size_t)((kq0 + u) * 4) * ne + code;
                wv[u*4+0] = __ldg(wr);
                wv[u*4+1] = __ldg(wr + ne);
                wv[u*4+2] = __ldg(wr + 2 * ne);
                wv[u*4+3] = __ldg(wr + 3 * ne);
            }
            #pragma unroll
            for (int u = 0; u < 4; ++u) {
                #pragma unroll
                for (int r = 0; r < 8; ++r) {
                    float4 xv = *(const float4*)&xs[r][(kq0 + u) * 4];
                    acc[r] = fmaf(xv.x, wv[u*4],
                             fmaf(xv.y, wv[u*4+1],
                             fmaf(xv.z, wv[u*4+2],
                             fmaf(xv.w, wv[u*4+3], acc[r]))));
                }
            }
        }

        float inv = __ldg(&g_inv_norm[code]);
        unsigned long long bk[8];
        #pragma unroll
        for (int r = 0; r < 8; ++r) bk[r] = pack_key(acc[r] * inv, code);
        #pragma unroll
        for (int r = 0; r < 8; ++r) {
            #pragma unroll
            for (int o = 16; o; o >>= 1) {
                unsigned long long ok = __shfl_down_sync(0xffffffffu, bk[r], o);
                if (ok > bk[r]) bk[r] = ok;
            }
        }
        if (lane == 0) {
            #pragma unroll
            for (int r = 0; r < 8; ++r)
                if (r < cnt) atomicMax(&g_best[g_flag[base + r]], bk[r]);
        }
    }
}

// ---- K5: gather + MSE + fused finalize (last-block pattern) ----
__global__ void gather_kernel(const float* __restrict__ x, const float* __restrict__ w,
                              float* __restrict__ out0, float* __restrict__ out_ind,
                              float* __restrict__ diff_out, float inv_cnt,
                              int write_extra, int n) {
    const int warp = threadIdx.x >> 5, lane = threadIdx.x & 31;
    const int row = blockIdx.x * 8 + warp;
    float lsum = 0.f;
    if (row < n) {
        int ind = g_ind[row];
        if (g_flag01[row])
            ind = (int)(0xFFFFFFFFu - (uint32_t)(g_best[row] & 0xFFFFFFFFull));
        const float sc = g_scale[ind];
        const float4* px = (const float4*)(x + (size_t)row * DIM);
        const float4* pw = (const float4*)(w + (size_t)ind * DIM);
        float4* po = (float4*)(out0 + (size_t)row * DIM);
        #pragma unroll
        for (int it = 0; it < 4; ++it) {
            int idx = it * 32 + lane;
            float4 wv = pw[idx], xv = px[idx];
            float4 q = make_float4(wv.x * sc, wv.y * sc, wv.z * sc, wv.w * sc);
            po[idx] = q;
            float dx = q.x - xv.x, dy = q.y - xv.y, dz = q.z - xv.z, dw = q.w - xv.w;
            lsum += dx * dx + dy * dy + dz * dz + dw * dw;
        }
        if (write_extra && lane == 0) out_ind[row] = (float)ind;
    }
    #pragma unroll
    for (int o = 16; o; o >>= 1) lsum += __shfl_down_sync(0xffffffffu, lsum, o);
    __shared__ float rs[8];
    if (lane == 0) rs[warp] = lsum;
    __syncthreads();
    if (threadIdx.x == 0) {
        float tt = 0.f;
        #pragma unroll
        for (int i = 0; i < 8; i++) tt += rs[i];
        atomicAdd(&g_diff, tt);
        __threadfence();
        int done = atomicAdd(&g_done, 1);
        if (write_extra && done == gridDim.x - 1)
            *diff_out = g_diff * inv_cnt;
    }
}

// ---- launch ----
extern "C" void kernel_launch(void* const* d_in, const int* in_sizes, int n_in,
                              void* d_out, int out_size) {
    const float* x = (const float*)d_in[0];
    const float* w = (const float*)d_in[1];
    int xe = in_sizes[0], we = (n_in >= 2) ? in_sizes[1] : 0;
    if (n_in >= 2 && we > xe) { const float* t = x; x = w; w = t; int te = xe; xe = we; we = te; }
    int n = xe / DIM, ne = we / DIM;
    if (n > MAXN) n = MAXN;
    if (ne > MAXNE) ne = MAXNE;
    float* out = (float*)d_out;
    const long long full = (long long)n * DIM + 1 + n;
    const int write_extra = (out_size >= full);

    __half* xh = (__half*)out;
    __half* wh = (__half*)(out + (size_t)n * DIM / 2);
    float*  wt = out + (size_t)n * DIM / 2 + (size_t)ne * DIM / 2;

    cudaFuncSetAttribute(gemm_argmax, cudaFuncAttributeMaxDynamicSharedMemorySize, 229376);

    prep_w<<<ne, 128>>>(w, wh, wt, ne);
    tohalf_kernel<<<(n * DIM / 4 + 255) / 256, 256>>>(x, xh, n * DIM / 4);
    gemm_argmax<<<(n + BM - 1) / BM, 256, 229376>>>(xh, wh, n, ne);
    recheck_kernel<<<512, 256>>>(x, wt, ne);
    gather_kernel<<<(n + 7) / 8, 256>>>(x, w, out,
                                        write_extra ? out + (size_t)n * DIM + 1 : out,
                                        out + (size_t)n * DIM,
                                        1.0f / ((float)n * (float)DIM),
                                        write_extra, n);
}

// round 15
// speedup vs baseline: 4.5301x; 1.0625x over previous
#include <cuda_runtime.h>
#include <cuda_fp16.h>
#include <math.h>
#include <stdint.h>

#define DIM    512
#define MAXN   32768
#define MAXNE  4096
#define MARGIN 4e-3f
#define BM 128

__device__ float g_inv_norm[MAXNE];
__device__ float g_scale[MAXNE];
__device__ int   g_ind[MAXN];
__device__ int   g_flag01[MAXN];
__device__ float g_diff;
__device__ int   g_nflag;
__device__ int   g_done;
__device__ int   g_flag[MAXN];
__device__ unsigned long long g_best[MAXN];

__device__ __forceinline__ uint32_t h2_bits(__half2 h) {
    uint32_t u;
    *(__half2*)&u = h;
    return u;
}
__device__ __forceinline__ uint32_t smem_u32(const void* p) {
    uint32_t a;
    asm("{ .reg .u64 t; cvta.to.shared.u64 t, %1; cvt.u32.u64 %0, t; }" : "=r"(a) : "l"(p));
    return a;
}
__device__ __forceinline__ void cpa16(uint32_t dst, const void* src) {
    asm volatile("cp.async.cg.shared.global [%0], [%1], 16;" :: "r"(dst), "l"(src) : "memory");
}
#define CPC()  asm volatile("cp.async.commit_group;" ::: "memory")
#define CPW(n) asm volatile("cp.async.wait_group %0;" :: "n"(n) : "memory")

__device__ __forceinline__ void ldsm4(uint32_t& a0, uint32_t& a1, uint32_t& a2, uint32_t& a3, uint32_t addr) {
    asm volatile("ldmatrix.sync.aligned.m8n8.x4.shared.b16 {%0,%1,%2,%3}, [%4];"
                 : "=r"(a0), "=r"(a1), "=r"(a2), "=r"(a3) : "r"(addr));
}
__device__ __forceinline__ void mma16816(float* c, const uint32_t* a, const uint32_t* b) {
    asm volatile("mma.sync.aligned.m16n8k16.row.col.f32.f16.f16.f32 "
                 "{%0,%1,%2,%3}, {%4,%5,%6,%7}, {%8,%9}, {%0,%1,%2,%3};"
                 : "+f"(c[0]), "+f"(c[1]), "+f"(c[2]), "+f"(c[3])
                 : "r"(a[0]), "r"(a[1]), "r"(a[2]), "r"(a[3]), "r"(b[0]), "r"(b[1]));
}
__device__ __forceinline__ void upd(float& b, float& s, int& i, float v, int col) {
    if (v > b) { s = b; b = v; i = col; } else if (v > s) s = v;
}
__device__ __forceinline__ void mrg(float& b, float& s, int& i, float ob, float os, int oi) {
    if (ob > b || (ob == b && oi < i)) { s = fmaxf(b, os); b = ob; i = oi; }
    else s = fmaxf(s, ob);
}
__device__ __forceinline__ unsigned long long pack_key(float m, int code) {
    uint32_t u = __float_as_uint(m);
    u = (u & 0x80000000u) ? ~u : (u | 0x80000000u);
    return ((unsigned long long)u << 32) | (0xFFFFFFFFu - (uint32_t)code);
}

// ---- K1: fused norms + w fp16 + w transpose + resets ----
__global__ void prep_w(const float* __restrict__ w, __half* __restrict__ wh,
                       float* __restrict__ wt, int ne) {
    int row = blockIdx.x;
    const float* wr = w + (size_t)row * DIM;
    float4 v = ((const float4*)wr)[threadIdx.x];
    float s = v.x*v.x + v.y*v.y + v.z*v.z + v.w*v.w;
    ((__half2*)(wh + (size_t)row * DIM))[threadIdx.x * 2]     = __floats2half2_rn(v.x, v.y);
    ((__half2*)(wh + (size_t)row * DIM))[threadIdx.x * 2 + 1] = __floats2half2_rn(v.z, v.w);
    int k = threadIdx.x * 4;
    wt[(size_t)k * ne + row] = v.x;
    wt[(size_t)(k + 1) * ne + row] = v.y;
    wt[(size_t)(k + 2) * ne + row] = v.z;
    wt[(size_t)(k + 3) * ne + row] = v.w;
    __shared__ float red[4];
    #pragma unroll
    for (int o = 16; o; o >>= 1) s += __shfl_down_sync(0xffffffffu, s, o);
    if ((threadIdx.x & 31) == 0) red[threadIdx.x >> 5] = s;
    __syncthreads();
    if (threadIdx.x == 0) {
        float t = red[0] + red[1] + red[2] + red[3];
        float nm = sqrtf(t);
        g_inv_norm[row] = 1.0f / nm;
        g_scale[row] = fminf(1.0f, 1.0f / fmaxf(nm, 1e-7f));
        if (row == 0) { g_diff = 0.f; g_nflag = 0; g_done = 0; }
    }
}

// ---- K2: HMMA GEMM + top-2 argmax ----
// 512 thr = 16 warps (4M x 4N), warp tile 32x32, CTA tile 128 rows x 128 codes.
// A (x) converted fp32->fp16 in-kernel, persistent in smem (128KB).
// B (w fp16) 3-stage cp.async pipeline (3 x 32KB). smem 224KB.
__global__ __launch_bounds__(512, 1)
void gemm_argmax(const float* __restrict__ x, const __half* __restrict__ wh,
                 int n, int ne) {
    extern __shared__ char sm[];
    const uint32_t sb = smem_u32(sm);
    const uint32_t sbB = sb + 131072;
    const int tid = threadIdx.x, lane = tid & 31, wid = tid >> 5;
    const int wm = wid >> 2, wn = wid & 3;
    const int rowBase = blockIdx.x * BM;
    const int tiles = ne >> 7;
    const int nchunks = tiles * 4;

    auto issueB = [&](int h, int st) {
        const int ctb = h >> 2, kb = h & 3;
        #pragma unroll
        for (int i = 0; i < 4; ++i) {
            int idx = tid + i * 512;         // 0..2047
            int sub = idx >> 10, rem = idx & 1023;
            int r = rem >> 3, c = rem & 7;
            uint32_t sw = (uint32_t)(sub * 16384 + r * 128 + ((c ^ (r & 7)) << 4));
            cpa16(sbB + st * 32768 + sw,
                  wh + (size_t)(ctb * 128 + r) * DIM + kb * 128 + sub * 64 + c * 8);
        }
        CPC();
    };

    issueB(0, 0);
    issueB(1, 1);

    // A fill: fp32 x -> fp16 smem, once.
    #pragma unroll
    for (int kb = 0; kb < 4; ++kb) {
        #pragma unroll
        for (int i = 0; i < 4; ++i) {
            int idx = tid + i * 512;
            int sub = idx >> 10, rem = idx & 1023;
            int r = rem >> 3, c = rem & 7;
            uint32_t sw = (uint32_t)(sub * 16384 + r * 128 + ((c ^ (r & 7)) << 4));
            int gr = rowBase + r; if (gr >= n) gr = n - 1;
            const float4* px = (const float4*)(x + (size_t)gr * DIM + kb * 128 + sub * 64 + c * 8);
            float4 v0 = __ldg(px);
            float4 v1 = __ldg(px + 1);
            uint4 hv;
            hv.x = h2_bits(__floats2half2_rn(v0.x, v0.y));
            hv.y = h2_bits(__floats2half2_rn(v0.z, v0.w));
            hv.z = h2_bits(__floats2half2_rn(v1.x, v1.y));
            hv.w = h2_bits(__floats2half2_rn(v1.z, v1.w));
            *(uint4*)(sm + (sw + kb * 32768)) = hv;
        }
    }

    float best[4], second[4];
    int bidx[4];
    #pragma unroll
    for (int s = 0; s < 4; ++s) { best[s] = -3.4e38f; second[s] = -3.4e38f; bidx[s] = 0; }

    float acc[2][4][4];
    #pragma unroll
    for (int mt = 0; mt < 2; ++mt)
        #pragma unroll
        for (int nt = 0; nt < 4; ++nt)
            #pragma unroll
            for (int k = 0; k < 4; ++k) acc[mt][nt][k] = 0.f;

    for (int g = 0; g < nchunks; ++g) {
        if (g == nchunks - 1) { CPW(0); } else { CPW(1); }
        __syncthreads();
        if (g + 2 < nchunks) issueB(g + 2, (g + 2) % 3);

        const uint32_t ablk = sb + (g & 3) * 32768;
        const uint32_t bblk = sbB + (g % 3) * 32768;
        #pragma unroll
        for (int ks = 0; ks < 8; ++ks) {
            const int sub = ks >> 2, ksl = ks & 3;
            const uint32_t abase = ablk + sub * 16384;
            const uint32_t bbase = bblk + sub * 16384;
            uint32_t a[2][4];
            #pragma unroll
            for (int mt = 0; mt < 2; ++mt) {
                int ar = wm * 32 + mt * 16 + (lane & 15);
                int kc = ksl * 2 + (lane >> 4);
                ldsm4(a[mt][0], a[mt][1], a[mt][2], a[mt][3],
                      abase + ar * 128 + ((kc ^ (ar & 7)) << 4));
            }
            uint32_t bq[2][4];
            #pragma unroll
            for (int p = 0; p < 2; ++p) {
                int br = wn * 32 + p * 16 + (lane & 7) + ((lane >> 4) << 3);
                int kc = ksl * 2 + ((lane >> 3) & 1);
                ldsm4(bq[p][0], bq[p][1], bq[p][2], bq[p][3],
                      bbase + br * 128 + ((kc ^ (br & 7)) << 4));
            }
            #pragma unroll
            for (int mt = 0; mt < 2; ++mt)
                #pragma unroll
                for (int nt = 0; nt < 4; ++nt)
                    mma16816(acc[mt][nt], a[mt], &bq[nt >> 1][(nt & 1) * 2]);
        }

        if ((g & 3) == 3) {
            const int ct = g >> 2;
            #pragma unroll
            for (int nt = 0; nt < 4; ++nt) {
                int col = ct * 128 + wn * 32 + nt * 8 + (lane & 3) * 2;
                float i0 = __ldg(&g_inv_norm[col]);
                float i1 = __ldg(&g_inv_norm[col + 1]);
                #pragma unroll
                for (int mt = 0; mt < 2; ++mt) {
                    int s0 = mt * 2, s1 = mt * 2 + 1;
                    upd(best[s0], second[s0], bidx[s0], acc[mt][nt][0] * i0, col);
                    upd(best[s0], second[s0], bidx[s0], acc[mt][nt][1] * i1, col + 1);
                    upd(best[s1], second[s1], bidx[s1], acc[mt][nt][2] * i0, col);
                    upd(best[s1], second[s1], bidx[s1], acc[mt][nt][3] * i1, col + 1);
                    acc[mt][nt][0] = 0.f; acc[mt][nt][1] = 0.f;
                    acc[mt][nt][2] = 0.f; acc[mt][nt][3] = 0.f;
                }
            }
        }
    }

    // lane merge over lane bits 0,1
    #pragma unroll
    for (int s = 0; s < 4; ++s) {
        #pragma unroll
        for (int d = 1; d <= 2; d <<= 1) {
            float ob = __shfl_xor_sync(0xffffffffu, best[s], d);
            float os = __shfl_xor_sync(0xffffffffu, second[s], d);
            int   oi = __shfl_xor_sync(0xffffffffu, bidx[s], d);
            mrg(best[s], second[s], bidx[s], ob, os, oi);
        }
    }

    // cross-warp merge over wn via smem [4][128]
    __syncthreads();
    float* mb = (float*)sm;
    float* ms = mb + 512;
    int*   mi = (int*)(ms + 512);
    if ((lane & 3) == 0) {
        #pragma unroll
        for (int s = 0; s < 4; ++s) {
            int row = wm * 32 + (s >> 1) * 16 + (s & 1) * 8 + (lane >> 2);
            mb[wn * 128 + row] = best[s];
            ms[wn * 128 + row] = second[s];
            mi[wn * 128 + row] = bidx[s];
        }
    }
    __syncthreads();
    if (tid < 128) {
        float bb2 = mb[tid], ss2 = ms[tid];
        int bi = mi[tid];
        #pragma unroll
        for (int w = 1; w < 4; ++w)
            mrg(bb2, ss2, bi, mb[w * 128 + tid], ms[w * 128 + tid], mi[w * 128 + tid]);
        int grow = rowBase + tid;
        if (grow < n) {
            g_ind[grow] = bi;
            int fl = (bb2 - ss2 < MARGIN) ? 1 : 0;
            g_flag01[grow] = fl;
            if (fl) {
                int pos = atomicAdd(&g_nflag, 1);
                if (pos < MAXN) g_flag[pos] = grow;
                g_best[grow] = 0ull;
            }
        }
    }
}

// ---- K3: exact fp32 recheck: (8-row group) x (256-code slice) items ----
__global__ __launch_bounds__(256, 1)
void recheck_kernel(const float* __restrict__ x, const float* __restrict__ wt, int ne) {
    __shared__ float xs[8][DIM];
    const int tid = threadIdx.x, lane = tid & 31;
    int nf = g_nflag; if (nf > MAXN) nf = MAXN;
    const int ngroups = (nf + 7) >> 3;
    const int nslice = ne >> 8;
    const int total = ngroups * nslice;

    for (int wk = blockIdx.x; wk < total; wk += gridDim.x) {
        const int grp = wk / nslice, slice = wk - grp * nslice;
        const int base = grp * 8;
        int cnt = nf - base; if (cnt > 8) cnt = 8;
        __syncthreads();
        for (int e = tid; e < cnt * DIM; e += 256) {
            int r = e >> 9, k = e & 511;
            xs[r][k] = x[(size_t)g_flag[base + r] * DIM + k];
        }
        __syncthreads();

        const int code = slice * 256 + tid;
        float acc[8];
        #pragma unroll
        for (int r = 0; r < 8; ++r) acc[r] = 0.f;

        for (int kq0 = 0; kq0 < DIM / 4; kq0 += 4) {
            float wv[16];
            #pragma unroll
            for (int u = 0; u < 4; ++u) {
                const float* wr = wt + (size_t)((kq0 + u) * 4) * ne + code;
                wv[u*4+0] = __ldg(wr);
                wv[u*4+1] = __ldg(wr + ne);
                wv[u*4+2] = __ldg(wr + 2 * ne);
                wv[u*4+3] = __ldg(wr + 3 * ne);
            }
            #pragma unroll
            for (int u = 0; u < 4; ++u) {
                #pragma unroll
                for (int r = 0; r < 8; ++r) {
                    float4 xv = *(const float4*)&xs[r][(kq0 + u) * 4];
                    acc[r] = fmaf(xv.x, wv[u*4],
                             fmaf(xv.y, wv[u*4+1],
                             fmaf(xv.z, wv[u*4+2],
                             fmaf(xv.w, wv[u*4+3], acc[r]))));
                }
            }
        }

        float inv = __ldg(&g_inv_norm[code]);
        unsigned long long bk[8];
        #pragma unroll
        for (int r = 0; r < 8; ++r) bk[r] = pack_key(acc[r] * inv, code);
        #pragma unroll
        for (int r = 0; r < 8; ++r) {
            #pragma unroll
            for (int o = 16; o; o >>= 1) {
                unsigned long long ok = __shfl_down_sync(0xffffffffu, bk[r], o);
                if (ok > bk[r]) bk[r] = ok;
            }
        }
        if (lane == 0) {
            #pragma unroll
            for (int r = 0; r < 8; ++r)
                if (r < cnt) atomicMax(&g_best[g_flag[base + r]], bk[r]);
        }
    }
}

// ---- K4: gather + MSE + fused finalize ----
__global__ void gather_kernel(const float* __restrict__ x, const float* __restrict__ w,
                              float* __restrict__ out0, float* __restrict__ out_ind,
                              float* __restrict__ diff_out, float inv_cnt,
                              int write_extra, int n) {
    const int warp = threadIdx.x >> 5, lane = threadIdx.x & 31;
    const int row = blockIdx.x * 8 + warp;
    float lsum = 0.f;
    if (row < n) {
        int ind = g_ind[row];
        if (g_flag01[row])
            ind = (int)(0xFFFFFFFFu - (uint32_t)(g_best[row] & 0xFFFFFFFFull));
        const float sc = g_scale[ind];
        const float4* px = (const float4*)(x + (size_t)row * DIM);
        const float4* pw = (const float4*)(w + (size_t)ind * DIM);
        float4* po = (float4*)(out0 + (size_t)row * DIM);
        #pragma unroll
        for (int it = 0; it < 4; ++it) {
            int idx = it * 32 + lane;
            float4 wv = pw[idx], xv = px[idx];
            float4 q = make_float4(wv.x * sc, wv.y * sc, wv.z * sc, wv.w * sc);
            po[idx] = q;
            float dx = q.x - xv.x, dy = q.y - xv.y, dz = q.z - xv.z, dw = q.w - xv.w;
            lsum += dx * dx + dy * dy + dz * dz + dw * dw;
        }
        if (write_extra && lane == 0) out_ind[row] = (float)ind;
    }
    #pragma unroll
    for (int o = 16; o; o >>= 1) lsum += __shfl_down_sync(0xffffffffu, lsum, o);
    __shared__ float rs[8];
    if (lane == 0) rs[warp] = lsum;
    __syncthreads();
    if (threadIdx.x == 0) {
        float tt = 0.f;
        #pragma unroll
        for (int i = 0; i < 8; i++) tt += rs[i];
        atomicAdd(&g_diff, tt);
        __threadfence();
        int done = atomicAdd(&g_done, 1);
        if (write_extra && done == gridDim.x - 1)
            *diff_out = g_diff * inv_cnt;
    }
}

// ---- launch ----
extern "C" void kernel_launch(void* const* d_in, const int* in_sizes, int n_in,
                              void* d_out, int out_size) {
    const float* x = (const float*)d_in[0];
    const float* w = (const float*)d_in[1];
    int xe = in_sizes[0], we = (n_in >= 2) ? in_sizes[1] : 0;
    if (n_in >= 2 && we > xe) { const float* t = x; x = w; w = t; int te = xe; xe = we; we = te; }
    int n = xe / DIM, ne = we / DIM;
    if (n > MAXN) n = MAXN;
    if (ne > MAXNE) ne = MAXNE;
    float* out = (float*)d_out;
    const long long full = (long long)n * DIM + 1 + n;
    const int write_extra = (out_size >= full);

    // scratch inside d_out (all overwritten by gather later)
    __half* wh = (__half*)out;
    float*  wt = out + (size_t)ne * DIM / 2;

    cudaFuncSetAttribute(gemm_argmax, cudaFuncAttributeMaxDynamicSharedMemorySize, 229376);

    prep_w<<<ne, 128>>>(w, wh, wt, ne);
    gemm_argmax<<<(n + BM - 1) / BM, 512, 229376>>>(x, wh, n, ne);
    recheck_kernel<<<512, 256>>>(x, wt, ne);
    gather_kernel<<<(n + 7) / 8, 256>>>(x, w, out,
                                        write_extra ? out + (size_t)n * DIM + 1 : out,
                                        out + (size_t)n * DIM,
                                        1.0f / ((float)n * (float)DIM),
                                        write_extra, n);
}